// round 2
// baseline (speedup 1.0000x reference)
#include <cuda_runtime.h>
#include <cuda_bf16.h>
#include <cstdint>

// Problem constants
#define B_    2
#define TQ_   1024
#define DIN_  4096
#define H_    32
#define G_    8
#define HD_   128
#define SPREV 1024
#define SKV   2048          // SPREV + TQ
#define BT_   (B_*TQ_)      // 2048

// ---------------- scratch (no allocation allowed -> __device__ globals) ---------
__device__ float g_q  [(size_t)BT_ * H_ * HD_];   // 2048 x 4096
__device__ float g_k  [(size_t)BT_ * G_ * HD_];   // 2048 x 1024
__device__ float g_v  [(size_t)BT_ * G_ * HD_];   // 2048 x 1024
__device__ float g_ctx[(size_t)BT_ * H_ * HD_];   // 2048 x 4096

// =============================================================================
// Generic NT SGEMM: C[m,n] = sum_k A[m,k] * B[n,k]
// A: [M,K] row-major, B: [N,K] row-major, C: [M,N] row-major.
// BM=BN=128, BK=8, 256 threads, 8x8 per-thread tile. All dims divisible -> no guards.
// =============================================================================
__global__ void __launch_bounds__(256) gemm_nt(const float* __restrict__ A,
                                               const float* __restrict__ Bm,
                                               float* __restrict__ C,
                                               int M, int N, int K)
{
    __shared__ float As[8][128];
    __shared__ float Bs[8][128];

    const int bx = blockIdx.x;          // N tile
    const int by = blockIdx.y;          // M tile
    const int tid = threadIdx.x;
    const int tx = tid & 15;            // 16 cols of threads
    const int ty = tid >> 4;            // 16 rows of threads

    const float* Ab = A  + (size_t)by * 128 * K;
    const float* Bb = Bm + (size_t)bx * 128 * K;

    const int lrow = tid >> 1;          // 0..127
    const int lcol = (tid & 1) * 4;     // 0 or 4

    float acc[8][8];
    #pragma unroll
    for (int i = 0; i < 8; i++)
        #pragma unroll
        for (int j = 0; j < 8; j++) acc[i][j] = 0.f;

    for (int k0 = 0; k0 < K; k0 += 8) {
        float4 a4 = *(const float4*)(Ab + (size_t)lrow * K + k0 + lcol);
        float4 b4 = *(const float4*)(Bb + (size_t)lrow * K + k0 + lcol);
        As[lcol + 0][lrow] = a4.x; As[lcol + 1][lrow] = a4.y;
        As[lcol + 2][lrow] = a4.z; As[lcol + 3][lrow] = a4.w;
        Bs[lcol + 0][lrow] = b4.x; Bs[lcol + 1][lrow] = b4.y;
        Bs[lcol + 2][lrow] = b4.z; Bs[lcol + 3][lrow] = b4.w;
        __syncthreads();

        #pragma unroll
        for (int k = 0; k < 8; k++) {
            float ar[8], br[8];
            *(float4*)(ar + 0) = *(const float4*)(&As[k][ty * 8 + 0]);
            *(float4*)(ar + 4) = *(const float4*)(&As[k][ty * 8 + 4]);
            *(float4*)(br + 0) = *(const float4*)(&Bs[k][tx * 8 + 0]);
            *(float4*)(br + 4) = *(const float4*)(&Bs[k][tx * 8 + 4]);
            #pragma unroll
            for (int i = 0; i < 8; i++)
                #pragma unroll
                for (int j = 0; j < 8; j++)
                    acc[i][j] += ar[i] * br[j];
        }
        __syncthreads();
    }

    #pragma unroll
    for (int i = 0; i < 8; i++) {
        float* crow = C + (size_t)(by * 128 + ty * 8 + i) * N + bx * 128 + tx * 8;
        *(float4*)(crow + 0) = make_float4(acc[i][0], acc[i][1], acc[i][2], acc[i][3]);
        *(float4*)(crow + 4) = make_float4(acc[i][4], acc[i][5], acc[i][6], acc[i][7]);
    }
}

// =============================================================================
// Per-head RMSNorm + RoPE.  One warp per head. Lane l owns dims {l, l+32, l+64, l+96},
// so rotate-half pairs (d, d±64) are lane-local.
// =============================================================================
__device__ __forceinline__ void norm_rope_head(float* __restrict__ outp,
                                               const float* __restrict__ inp,
                                               const float* __restrict__ w,
                                               const float* __restrict__ cosT,
                                               const float* __restrict__ sinT,
                                               int pos, int l)
{
    float v0 = inp[l], v1 = inp[l + 32], v2 = inp[l + 64], v3 = inp[l + 96];
    float ss = v0 * v0 + v1 * v1 + v2 * v2 + v3 * v3;
    #pragma unroll
    for (int off = 16; off; off >>= 1) ss += __shfl_xor_sync(0xffffffffu, ss, off);
    float rinv = rsqrtf(ss * (1.f / 128.f) + 1e-6f);
    v0 *= rinv * w[l];      v1 *= rinv * w[l + 32];
    v2 *= rinv * w[l + 64]; v3 *= rinv * w[l + 96];
    const float* c = cosT + (size_t)pos * 128;
    const float* s = sinT + (size_t)pos * 128;
    float o0 = v0 * c[l]      - v2 * s[l];
    float o1 = v1 * c[l + 32] - v3 * s[l + 32];
    float o2 = v2 * c[l + 64] + v0 * s[l + 64];
    float o3 = v3 * c[l + 96] + v1 * s[l + 96];
    outp[l] = o0; outp[l + 32] = o1; outp[l + 64] = o2; outp[l + 96] = o3;
}

__global__ void q_norm_rope(float* __restrict__ q, const float* __restrict__ w,
                            const float* __restrict__ cosT, const float* __restrict__ sinT,
                            const int* __restrict__ pid)
{
    int bt = blockIdx.x;                  // 0..2047
    int h  = threadIdx.x >> 5;
    int l  = threadIdx.x & 31;
    float* base = q + ((size_t)bt * H_ + h) * HD_;
    norm_rope_head(base, base, w, cosT, sinT, pid[bt], l);
}

__global__ void k_norm_rope_scatter(const float* __restrict__ kproj,
                                    float* __restrict__ kall,
                                    const float* __restrict__ w,
                                    const float* __restrict__ cosT,
                                    const float* __restrict__ sinT,
                                    const int* __restrict__ pid)
{
    int bt = blockIdx.x;
    int b = bt >> 10, t = bt & 1023;
    int g = threadIdx.x >> 5;
    int l = threadIdx.x & 31;
    const float* src = kproj + ((size_t)bt * G_ + g) * HD_;
    float* dst = kall + (((size_t)(b * G_ + g) * SKV) + SPREV + t) * HD_;
    norm_rope_head(dst, src, w, cosT, sinT, pid[bt], l);
}

// v_proj [b,t,g,d] -> v_all [b,g,SPREV+t,d]   (float4 granularity)
__global__ void v_scatter(const float* __restrict__ vp, float* __restrict__ vall)
{
    size_t i = (size_t)blockIdx.x * blockDim.x + threadIdx.x;  // 524288 float4s
    int d4 = i & 31;
    int g  = (i >> 5) & 7;
    int bt = (int)(i >> 8);
    int b = bt >> 10, t = bt & 1023;
    size_t dst = (((size_t)(b * G_ + g) * SKV) + SPREV + t) * 32 + d4;
    ((float4*)vall)[dst] = ((const float4*)vp)[i];
}

// prev_k/prev_v [b,g,s,d] -> k_all/v_all [b,g,s,d]  (first SPREV rows)
__global__ void prev_scatter(const float* __restrict__ pk, const float* __restrict__ pv,
                             float* __restrict__ kall, float* __restrict__ vall)
{
    size_t i = (size_t)blockIdx.x * blockDim.x + threadIdx.x;  // 524288 float4s
    int d4 = i & 31;
    int s  = (i >> 5) & 1023;
    int bg = (int)(i >> 15);                    // 0..15
    size_t dst = ((size_t)bg * SKV + s) * 32 + d4;
    ((float4*)kall)[dst] = ((const float4*)pk)[i];
    ((float4*)vall)[dst] = ((const float4*)pv)[i];
}

// =============================================================================
// Flash attention, fp32. Block = 256 threads handles (b, h, 64-query tile).
// KV tile = 32. Thread (r = tid/4, cg = tid%4): owns query row r, score cols
// cg*8..cg*8+7, output cols cg*32..cg*32+31.
// =============================================================================
#define QT 64
#define KT 32
#define ATTN_SMEM ((QT*128 + KT*128 + KT*128 + QT*KT) * 4)   // 73728 B

__global__ void __launch_bounds__(256) attn_kernel(const float* __restrict__ q,
                                                   const float* __restrict__ kall,
                                                   const float* __restrict__ vall,
                                                   float* __restrict__ ctx)
{
    extern __shared__ float sm[];
    float* Qs = sm;                 // QT x 128
    float* Ks = Qs + QT * 128;      // KT x 128
    float* Vs = Ks + KT * 128;      // KT x 128
    float* Ps = Vs + KT * 128;      // QT x KT

    const int t0 = blockIdx.x * QT;
    const int h  = blockIdx.y;
    const int b  = blockIdx.z;
    const int g  = h >> 2;          // H/G = 4
    const int tid = threadIdx.x;

    // load Q tile
    const float* qbase = q + ((size_t)(b * TQ_ + t0) * H_ + h) * HD_;
    #pragma unroll
    for (int i = tid; i < QT * 32; i += 256) {       // float4 units
        int row = i >> 5, c4 = i & 31;
        *(float4*)(Qs + row * 128 + c4 * 4) =
            *(const float4*)(qbase + (size_t)row * (H_ * HD_) + c4 * 4);
    }

    const int r  = tid >> 2;
    const int cg = tid & 3;
    float o[32];
    #pragma unroll
    for (int i = 0; i < 32; i++) o[i] = 0.f;
    float m_i = -1e30f, l_i = 0.f;
    const float scale = 0.08838834764831845f;        // 1/sqrt(128)
    const int qpos = SPREV + t0 + r;

    int kv_lim = SPREV + t0 + QT;                    // exclusive bound for this block
    if (kv_lim > SKV) kv_lim = SKV;

    const float* kb = kall + (size_t)(b * G_ + g) * SKV * HD_;
    const float* vb = vall + (size_t)(b * G_ + g) * SKV * HD_;

    __syncthreads();

    for (int j0 = 0; j0 < kv_lim; j0 += KT) {
        // load K,V tiles (KT*32 float4 each, 4 per thread)
        #pragma unroll
        for (int i = tid; i < KT * 32; i += 256) {
            int row = i >> 5, c4 = i & 31;
            *(float4*)(Ks + row * 128 + c4 * 4) =
                *(const float4*)(kb + (size_t)(j0 + row) * 128 + c4 * 4);
            *(float4*)(Vs + row * 128 + c4 * 4) =
                *(const float4*)(vb + (size_t)(j0 + row) * 128 + c4 * 4);
        }
        __syncthreads();

        // scores: 8 dots of length 128
        float s[8];
        #pragma unroll
        for (int j = 0; j < 8; j++) s[j] = 0.f;
        for (int kk = 0; kk < 128; kk += 4) {
            float4 qv = *(const float4*)(Qs + r * 128 + kk);
            #pragma unroll
            for (int j = 0; j < 8; j++) {
                float4 k4 = *(const float4*)(Ks + (cg * 8 + j) * 128 + kk);
                s[j] += qv.x * k4.x + qv.y * k4.y + qv.z * k4.z + qv.w * k4.w;
            }
        }

        // mask + scale + local max
        float mloc = -1e30f;
        #pragma unroll
        for (int j = 0; j < 8; j++) {
            int jg = j0 + cg * 8 + j;
            s[j] = (jg <= qpos) ? s[j] * scale : -1e30f;
            mloc = fmaxf(mloc, s[j]);
        }
        mloc = fmaxf(mloc, __shfl_xor_sync(0xffffffffu, mloc, 1));
        mloc = fmaxf(mloc, __shfl_xor_sync(0xffffffffu, mloc, 2));
        float m_new = fmaxf(m_i, mloc);
        float alpha = __expf(m_i - m_new);

        float lsum = 0.f;
        #pragma unroll
        for (int j = 0; j < 8; j++) {
            float p = __expf(s[j] - m_new);
            Ps[r * KT + cg * 8 + j] = p;
            lsum += p;
        }
        lsum += __shfl_xor_sync(0xffffffffu, lsum, 1);
        lsum += __shfl_xor_sync(0xffffffffu, lsum, 2);
        l_i = l_i * alpha + lsum;
        m_i = m_new;
        #pragma unroll
        for (int i = 0; i < 32; i++) o[i] *= alpha;
        __syncwarp();        // Ps row r written/read by lanes 4r..4r+3 (same warp)

        // PV
        #pragma unroll 4
        for (int j = 0; j < KT; j++) {
            float p = Ps[r * KT + j];
            const float* vrow = Vs + j * 128 + cg * 32;
            #pragma unroll
            for (int c = 0; c < 32; c += 4) {
                float4 vv = *(const float4*)(vrow + c);
                o[c + 0] += p * vv.x; o[c + 1] += p * vv.y;
                o[c + 2] += p * vv.z; o[c + 3] += p * vv.w;
            }
        }
        __syncthreads();     // protect Ks/Vs/Ps before next tile load
    }

    float inv = 1.f / l_i;
    float* obase = ctx + ((size_t)(b * TQ_ + t0 + r) * H_ + h) * HD_ + cg * 32;
    #pragma unroll
    for (int c = 0; c < 32; c += 4)
        *(float4*)(obase + c) = make_float4(o[c] * inv, o[c + 1] * inv,
                                            o[c + 2] * inv, o[c + 3] * inv);
}

// =============================================================================
// host launcher
// =============================================================================
static float* sym_addr(const void* symbol)
{
    void* p = nullptr;
    cudaGetSymbolAddress(&p, symbol);
    return (float*)p;
}

extern "C" void kernel_launch(void* const* d_in, const int* in_sizes, int n_in,
                              void* d_out, int out_size)
{
    const float* x    = (const float*)d_in[0];
    const float* Wq   = (const float*)d_in[1];
    const float* Wk   = (const float*)d_in[2];
    const float* Wv   = (const float*)d_in[3];
    const float* Wo   = (const float*)d_in[4];
    const float* qw   = (const float*)d_in[5];
    const float* kw   = (const float*)d_in[6];
    const float* cosT = (const float*)d_in[7];
    const float* sinT = (const float*)d_in[8];
    const float* pk   = (const float*)d_in[9];
    const float* pv   = (const float*)d_in[10];
    const int*   pid  = (const int*)d_in[11];
    // d_in[12] = mask, computed analytically instead

    float* out  = (float*)d_out;                                    // B*T*DIN
    float* kall = out  + (size_t)B_ * TQ_ * DIN_;                   // B*G*SKV*HD
    float* vall = kall + (size_t)B_ * G_ * SKV * HD_;

    float* q   = sym_addr(g_q);
    float* k   = sym_addr(g_k);
    float* v   = sym_addr(g_v);
    float* ctx = sym_addr(g_ctx);

    // QKV projections (NT gemms)
    gemm_nt<<<dim3(DIN_ / 128, BT_ / 128), 256>>>(x, Wq, q, BT_, DIN_, DIN_);
    gemm_nt<<<dim3(G_ * HD_ / 128, BT_ / 128), 256>>>(x, Wk, k, BT_, G_ * HD_, DIN_);
    gemm_nt<<<dim3(G_ * HD_ / 128, BT_ / 128), 256>>>(x, Wv, v, BT_, G_ * HD_, DIN_);

    // norm + rope + kv-cache assembly
    q_norm_rope<<<BT_, H_ * 32>>>(q, qw, cosT, sinT, pid);
    k_norm_rope_scatter<<<BT_, G_ * 32>>>(k, kall, kw, cosT, sinT, pid);
    v_scatter<<<2048, 256>>>(v, vall);
    prev_scatter<<<2048, 256>>>(pk, pv, kall, vall);

    // attention
    cudaFuncSetAttribute(attn_kernel, cudaFuncAttributeMaxDynamicSharedMemorySize, ATTN_SMEM);
    attn_kernel<<<dim3(TQ_ / QT, H_, B_), 256, ATTN_SMEM>>>(q, kall, vall, ctx);

    // output projection
    gemm_nt<<<dim3(DIN_ / 128, BT_ / 128), 256>>>(ctx, Wo, out, BT_, DIN_, DIN_);

    (void)in_sizes; (void)n_in; (void)out_size;
}

// round 3
// speedup vs baseline: 5.1606x; 5.1606x over previous
#include <cuda_runtime.h>
#include <cuda_bf16.h>
#include <cstdint>

// Problem constants
#define B_    2
#define TQ_   1024
#define DIN_  4096
#define H_    32
#define G_    8
#define HD_   128
#define SPREV 1024
#define SKV   2048          // SPREV + TQ
#define BT_   (B_*TQ_)      // 2048

// ---------------- scratch (no allocation allowed -> __device__ globals) ---------
__device__ float g_q  [(size_t)BT_ * H_ * HD_];   // 2048 x 4096
__device__ float g_k  [(size_t)BT_ * G_ * HD_];   // 2048 x 1024
__device__ float g_v  [(size_t)BT_ * G_ * HD_];   // 2048 x 1024
__device__ float g_ctx[(size_t)BT_ * H_ * HD_];   // 2048 x 4096

// =============================================================================
// tf32 tensor-core NT GEMM: C[m,n] = sum_k A[m,k]*B[n,k]
// Tile 128x128x32, 128 threads (4 warps, each 64x64), mma.sync m16n8k8 tf32,
// cp.async double-buffered smem, pitch 36 floats (conflict-free frag loads).
// =============================================================================
__device__ __forceinline__ void cp16(void* s, const void* g){
    unsigned sa = (unsigned)__cvta_generic_to_shared(s);
    asm volatile("cp.async.cg.shared.global [%0], [%1], 16;\n" :: "r"(sa), "l"(g));
}
__device__ __forceinline__ void cp_commit(){ asm volatile("cp.async.commit_group;\n" ::); }
template<int NN> __device__ __forceinline__ void cp_wait(){
    asm volatile("cp.async.wait_group %0;\n" :: "n"(NN));
}
__device__ __forceinline__ unsigned f2tf(float x){
    unsigned r; asm("cvt.rna.tf32.f32 %0, %1;" : "=r"(r) : "f"(x)); return r;
}
__device__ __forceinline__ void mma_tf32(float* c, const unsigned* a, const unsigned* b){
    asm volatile(
      "mma.sync.aligned.m16n8k8.row.col.f32.tf32.tf32.f32 "
      "{%0,%1,%2,%3}, {%4,%5,%6,%7}, {%8,%9}, {%0,%1,%2,%3};"
      : "+f"(c[0]), "+f"(c[1]), "+f"(c[2]), "+f"(c[3])
      : "r"(a[0]), "r"(a[1]), "r"(a[2]), "r"(a[3]), "r"(b[0]), "r"(b[1]));
}

#define GP 36                       // smem pitch (floats)
#define GEMM_SMEM (2 * 128 * GP * 2 * 4)   // 73728 B

__global__ void __launch_bounds__(128) gemm_tf32(const float* __restrict__ A,
                                                 const float* __restrict__ Bm,
                                                 float* __restrict__ C,
                                                 int M, int N, int K)
{
    extern __shared__ float sh[];
    float* As = sh;                  // 2 x [128][GP]
    float* Bs = sh + 2 * 128 * GP;   // 2 x [128][GP]

    const int tid  = threadIdx.x;
    const int lane = tid & 31, warp = tid >> 5;
    const int g  = lane >> 2, tg = lane & 3;
    const int wm = (warp >> 1) * 64, wn = (warp & 1) * 64;

    const float* Ag = A  + (size_t)blockIdx.y * 128 * K;
    const float* Bg = Bm + (size_t)blockIdx.x * 128 * K;

    float c[4][8][4];
    #pragma unroll
    for (int i = 0; i < 4; i++)
        #pragma unroll
        for (int j = 0; j < 8; j++)
            #pragma unroll
            for (int t = 0; t < 4; t++) c[i][j][t] = 0.f;

    const int nkt = K >> 5;

#define STAGE(buf, kt) do {                                                  \
    float* da = As + (buf) * 128 * GP;                                       \
    float* db = Bs + (buf) * 128 * GP;                                       \
    const float* sa = Ag + (size_t)(kt) * 32;                                \
    const float* sb = Bg + (size_t)(kt) * 32;                                \
    _Pragma("unroll")                                                        \
    for (int i = 0; i < 8; i++){                                             \
        int idx = i * 128 + tid; int row = idx >> 3; int c4 = (idx & 7) * 4; \
        cp16(da + row * GP + c4, sa + (size_t)row * K + c4);                 \
        cp16(db + row * GP + c4, sb + (size_t)row * K + c4);                 \
    }                                                                        \
} while (0)

    STAGE(0, 0); cp_commit();

    for (int kt = 0; kt < nkt; kt++) {
        if (kt + 1 < nkt) { STAGE((kt + 1) & 1, kt + 1); cp_commit(); cp_wait<1>(); }
        else              { cp_wait<0>(); }
        __syncthreads();

        const float* Ab = As + (kt & 1) * 128 * GP;
        const float* Bb = Bs + (kt & 1) * 128 * GP;

        #pragma unroll
        for (int ks = 0; ks < 4; ks++) {
            const int kc = ks * 8;
            unsigned a[4][4], bfr[8][2];
            #pragma unroll
            for (int f = 0; f < 4; f++) {
                int ra = wm + f * 16 + g;
                a[f][0] = f2tf(Ab[ra       * GP + kc + tg]);
                a[f][1] = f2tf(Ab[(ra + 8) * GP + kc + tg]);
                a[f][2] = f2tf(Ab[ra       * GP + kc + tg + 4]);
                a[f][3] = f2tf(Ab[(ra + 8) * GP + kc + tg + 4]);
            }
            #pragma unroll
            for (int f = 0; f < 8; f++) {
                int rb = wn + f * 8 + g;
                bfr[f][0] = f2tf(Bb[rb * GP + kc + tg]);
                bfr[f][1] = f2tf(Bb[rb * GP + kc + tg + 4]);
            }
            #pragma unroll
            for (int i = 0; i < 4; i++)
                #pragma unroll
                for (int j = 0; j < 8; j++)
                    mma_tf32(c[i][j], a[i], bfr[j]);
        }
        __syncthreads();
    }
#undef STAGE

    // epilogue
    #pragma unroll
    for (int i = 0; i < 4; i++) {
        int row0 = blockIdx.y * 128 + wm + i * 16 + g;
        #pragma unroll
        for (int j = 0; j < 8; j++) {
            int col = blockIdx.x * 128 + wn + j * 8 + 2 * tg;
            *(float2*)(C + (size_t)row0 * N + col)       = make_float2(c[i][j][0], c[i][j][1]);
            *(float2*)(C + (size_t)(row0 + 8) * N + col) = make_float2(c[i][j][2], c[i][j][3]);
        }
    }
}

// =============================================================================
// Per-head RMSNorm + RoPE.  One warp per head; lane l owns dims {l,l+32,l+64,l+96}.
// =============================================================================
__device__ __forceinline__ void norm_rope_head(float* __restrict__ outp,
                                               const float* __restrict__ inp,
                                               const float* __restrict__ w,
                                               const float* __restrict__ cosT,
                                               const float* __restrict__ sinT,
                                               int pos, int l)
{
    float v0 = inp[l], v1 = inp[l + 32], v2 = inp[l + 64], v3 = inp[l + 96];
    float ss = v0 * v0 + v1 * v1 + v2 * v2 + v3 * v3;
    #pragma unroll
    for (int off = 16; off; off >>= 1) ss += __shfl_xor_sync(0xffffffffu, ss, off);
    float rinv = rsqrtf(ss * (1.f / 128.f) + 1e-6f);
    v0 *= rinv * w[l];      v1 *= rinv * w[l + 32];
    v2 *= rinv * w[l + 64]; v3 *= rinv * w[l + 96];
    const float* c = cosT + (size_t)pos * 128;
    const float* s = sinT + (size_t)pos * 128;
    float o0 = v0 * c[l]      - v2 * s[l];
    float o1 = v1 * c[l + 32] - v3 * s[l + 32];
    float o2 = v2 * c[l + 64] + v0 * s[l + 64];
    float o3 = v3 * c[l + 96] + v1 * s[l + 96];
    outp[l] = o0; outp[l + 32] = o1; outp[l + 64] = o2; outp[l + 96] = o3;
}

__global__ void q_norm_rope(float* __restrict__ q, const float* __restrict__ w,
                            const float* __restrict__ cosT, const float* __restrict__ sinT,
                            const int* __restrict__ pid)
{
    int bt = blockIdx.x;
    int h  = threadIdx.x >> 5;
    int l  = threadIdx.x & 31;
    float* base = q + ((size_t)bt * H_ + h) * HD_;
    norm_rope_head(base, base, w, cosT, sinT, pid[bt], l);
}

__global__ void k_norm_rope_scatter(const float* __restrict__ kproj,
                                    float* __restrict__ kall,
                                    const float* __restrict__ w,
                                    const float* __restrict__ cosT,
                                    const float* __restrict__ sinT,
                                    const int* __restrict__ pid)
{
    int bt = blockIdx.x;
    int b = bt >> 10, t = bt & 1023;
    int g = threadIdx.x >> 5;
    int l = threadIdx.x & 31;
    const float* src = kproj + ((size_t)bt * G_ + g) * HD_;
    float* dst = kall + (((size_t)(b * G_ + g) * SKV) + SPREV + t) * HD_;
    norm_rope_head(dst, src, w, cosT, sinT, pid[bt], l);
}

__global__ void v_scatter(const float* __restrict__ vp, float* __restrict__ vall)
{
    size_t i = (size_t)blockIdx.x * blockDim.x + threadIdx.x;  // 524288 float4s
    int d4 = i & 31;
    int g  = (i >> 5) & 7;
    int bt = (int)(i >> 8);
    int b = bt >> 10, t = bt & 1023;
    size_t dst = (((size_t)(b * G_ + g) * SKV) + SPREV + t) * 32 + d4;
    ((float4*)vall)[dst] = ((const float4*)vp)[i];
}

__global__ void prev_scatter(const float* __restrict__ pk, const float* __restrict__ pv,
                             float* __restrict__ kall, float* __restrict__ vall)
{
    size_t i = (size_t)blockIdx.x * blockDim.x + threadIdx.x;  // 524288 float4s
    int d4 = i & 31;
    int s  = (i >> 5) & 1023;
    int bg = (int)(i >> 15);
    size_t dst = ((size_t)bg * SKV + s) * 32 + d4;
    ((float4*)kall)[dst] = ((const float4*)pk)[i];
    ((float4*)vall)[dst] = ((const float4*)pv)[i];
}

// =============================================================================
// Flash attention, fp32, 2 query rows per thread, bank-swizzled smem.
// Block = 256 threads = (b, h, 128-query tile). KV tile = 32.
// Thread (r = tid/4, cg = tid%4): rows r and r+64, score cols cg*8..+7,
// output cols cg*32..+31.
// Swizzles: Qs col ^ ((row&7)<<2); Ks col ^ (((row>>3)&3)<<2);
//           Vs (col&31) ^ (((col>>5)&3)<<3); Ps pitch 33.
// =============================================================================
#define QT 128
#define KT 32
#define ATTN_SMEM ((QT*128 + KT*128 + KT*128 + QT*33) * 4)   // 115200 B

__global__ void __launch_bounds__(256) attn_kernel(const float* __restrict__ q,
                                                   const float* __restrict__ kall,
                                                   const float* __restrict__ vall,
                                                   float* __restrict__ ctx)
{
    extern __shared__ float sm[];
    float* Qs = sm;                 // QT x 128 (swizzled)
    float* Ks = Qs + QT * 128;      // KT x 128 (swizzled)
    float* Vs = Ks + KT * 128;      // KT x 128 (swizzled)
    float* Ps = Vs + KT * 128;      // QT x 33

    const int t0 = blockIdx.x * QT;
    const int h  = blockIdx.y;
    const int b  = blockIdx.z;
    const int g  = h >> 2;          // H/G = 4
    const int tid = threadIdx.x;

    // load Q tile (swizzled)
    const float* qbase = q + ((size_t)(b * TQ_ + t0) * H_ + h) * HD_;
    for (int i = tid; i < QT * 32; i += 256) {
        int row = i >> 5, col = (i & 31) * 4;
        int sc = col ^ ((row & 7) << 2);
        *(float4*)(Qs + row * 128 + sc) =
            *(const float4*)(qbase + (size_t)row * (H_ * HD_) + col);
    }

    const int r  = tid >> 2;        // 0..63
    const int cg = tid & 3;
    float o0[32], o1[32];
    #pragma unroll
    for (int i = 0; i < 32; i++) { o0[i] = 0.f; o1[i] = 0.f; }
    float m0 = -1e30f, m1 = -1e30f, l0 = 0.f, l1 = 0.f;
    const float scale = 0.08838834764831845f;        // 1/sqrt(128)
    const int qp0 = SPREV + t0 + r;
    const int qp1 = qp0 + 64;

    int kv_lim = SPREV + t0 + QT;
    if (kv_lim > SKV) kv_lim = SKV;

    const float* kb = kall + (size_t)(b * G_ + g) * SKV * HD_;
    const float* vb = vall + (size_t)(b * G_ + g) * SKV * HD_;

    __syncthreads();

    for (int j0 = 0; j0 < kv_lim; j0 += KT) {
        // load K,V tiles (swizzled), 1024 float4s, 4 per thread
        for (int i = tid; i < KT * 32; i += 256) {
            int row = i >> 5, col = (i & 31) * 4;
            int sk = col ^ (((row >> 3) & 3) << 2);
            *(float4*)(Ks + row * 128 + sk) =
                *(const float4*)(kb + (size_t)(j0 + row) * 128 + col);
            int cgv = col >> 5;
            int sv  = cgv * 32 + ((col & 31) ^ (cgv << 3));
            *(float4*)(Vs + row * 128 + sv) =
                *(const float4*)(vb + (size_t)(j0 + row) * 128 + col);
        }
        __syncthreads();

        // scores: 2 rows x 8 cols, dots of length 128
        float s0[8], s1[8];
        #pragma unroll
        for (int j = 0; j < 8; j++) { s0[j] = 0.f; s1[j] = 0.f; }
        #pragma unroll 8
        for (int kk = 0; kk < 128; kk += 4) {
            int sq = kk ^ ((r & 7) << 2);
            float4 q0 = *(const float4*)(Qs + r * 128 + sq);
            float4 q1 = *(const float4*)(Qs + (r + 64) * 128 + sq);
            int skc = kk ^ (cg << 2);
            #pragma unroll
            for (int j = 0; j < 8; j++) {
                float4 k4 = *(const float4*)(Ks + (cg * 8 + j) * 128 + skc);
                s0[j] += q0.x * k4.x + q0.y * k4.y + q0.z * k4.z + q0.w * k4.w;
                s1[j] += q1.x * k4.x + q1.y * k4.y + q1.z * k4.z + q1.w * k4.w;
            }
        }

        // mask + scale + local max (per row)
        float ml0 = -1e30f, ml1 = -1e30f;
        #pragma unroll
        for (int j = 0; j < 8; j++) {
            int jg = j0 + cg * 8 + j;
            s0[j] = (jg <= qp0) ? s0[j] * scale : -1e30f;
            s1[j] = (jg <= qp1) ? s1[j] * scale : -1e30f;
            ml0 = fmaxf(ml0, s0[j]);
            ml1 = fmaxf(ml1, s1[j]);
        }
        ml0 = fmaxf(ml0, __shfl_xor_sync(0xffffffffu, ml0, 1));
        ml0 = fmaxf(ml0, __shfl_xor_sync(0xffffffffu, ml0, 2));
        ml1 = fmaxf(ml1, __shfl_xor_sync(0xffffffffu, ml1, 1));
        ml1 = fmaxf(ml1, __shfl_xor_sync(0xffffffffu, ml1, 2));
        float mn0 = fmaxf(m0, ml0), mn1 = fmaxf(m1, ml1);
        float al0 = __expf(m0 - mn0), al1 = __expf(m1 - mn1);

        float ls0 = 0.f, ls1 = 0.f;
        #pragma unroll
        for (int j = 0; j < 8; j++) {
            float p0 = __expf(s0[j] - mn0);
            float p1 = __expf(s1[j] - mn1);
            Ps[r * 33 + cg * 8 + j]        = p0;
            Ps[(r + 64) * 33 + cg * 8 + j] = p1;
            ls0 += p0; ls1 += p1;
        }
        ls0 += __shfl_xor_sync(0xffffffffu, ls0, 1);
        ls0 += __shfl_xor_sync(0xffffffffu, ls0, 2);
        ls1 += __shfl_xor_sync(0xffffffffu, ls1, 1);
        ls1 += __shfl_xor_sync(0xffffffffu, ls1, 2);
        l0 = l0 * al0 + ls0;  m0 = mn0;
        l1 = l1 * al1 + ls1;  m1 = mn1;
        #pragma unroll
        for (int i = 0; i < 32; i++) { o0[i] *= al0; o1[i] *= al1; }
        __syncwarp();        // Ps rows shared among 4 cg lanes of the same warp

        // PV (V rows shared between the 2 query rows)
        #pragma unroll 4
        for (int j = 0; j < KT; j++) {
            float p0 = Ps[r * 33 + j];
            float p1 = Ps[(r + 64) * 33 + j];
            const float* vrow = Vs + j * 128 + cg * 32;
            #pragma unroll
            for (int cc = 0; cc < 32; cc += 4) {
                int sv = cc ^ (cg << 3);
                float4 vv = *(const float4*)(vrow + sv);
                o0[cc + 0] += p0 * vv.x; o0[cc + 1] += p0 * vv.y;
                o0[cc + 2] += p0 * vv.z; o0[cc + 3] += p0 * vv.w;
                o1[cc + 0] += p1 * vv.x; o1[cc + 1] += p1 * vv.y;
                o1[cc + 2] += p1 * vv.z; o1[cc + 3] += p1 * vv.w;
            }
        }
        __syncthreads();     // protect Ks/Vs/Ps before next tile load
    }

    float i0 = 1.f / l0, i1 = 1.f / l1;
    float* ob0 = ctx + ((size_t)(b * TQ_ + t0 + r) * H_ + h) * HD_ + cg * 32;
    float* ob1 = ctx + ((size_t)(b * TQ_ + t0 + r + 64) * H_ + h) * HD_ + cg * 32;
    #pragma unroll
    for (int cc = 0; cc < 32; cc += 4) {
        *(float4*)(ob0 + cc) = make_float4(o0[cc] * i0, o0[cc + 1] * i0,
                                           o0[cc + 2] * i0, o0[cc + 3] * i0);
        *(float4*)(ob1 + cc) = make_float4(o1[cc] * i1, o1[cc + 1] * i1,
                                           o1[cc + 2] * i1, o1[cc + 3] * i1);
    }
}

// =============================================================================
// host launcher
// =============================================================================
static float* sym_addr(const void* symbol)
{
    void* p = nullptr;
    cudaGetSymbolAddress(&p, symbol);
    return (float*)p;
}

extern "C" void kernel_launch(void* const* d_in, const int* in_sizes, int n_in,
                              void* d_out, int out_size)
{
    const float* x    = (const float*)d_in[0];
    const float* Wq   = (const float*)d_in[1];
    const float* Wk   = (const float*)d_in[2];
    const float* Wv   = (const float*)d_in[3];
    const float* Wo   = (const float*)d_in[4];
    const float* qw   = (const float*)d_in[5];
    const float* kw   = (const float*)d_in[6];
    const float* cosT = (const float*)d_in[7];
    const float* sinT = (const float*)d_in[8];
    const float* pk   = (const float*)d_in[9];
    const float* pv   = (const float*)d_in[10];
    const int*   pid  = (const int*)d_in[11];
    // d_in[12] = mask, computed analytically

    float* out  = (float*)d_out;                                    // B*T*DIN
    float* kall = out  + (size_t)B_ * TQ_ * DIN_;                   // B*G*SKV*HD
    float* vall = kall + (size_t)B_ * G_ * SKV * HD_;

    float* q   = sym_addr(g_q);
    float* k   = sym_addr(g_k);
    float* v   = sym_addr(g_v);
    float* ctx = sym_addr(g_ctx);

    cudaFuncSetAttribute(gemm_tf32, cudaFuncAttributeMaxDynamicSharedMemorySize, GEMM_SMEM);
    cudaFuncSetAttribute(attn_kernel, cudaFuncAttributeMaxDynamicSharedMemorySize, ATTN_SMEM);

    // QKV projections (tf32 tensor-core NT gemms)
    gemm_tf32<<<dim3(DIN_ / 128, BT_ / 128), 128, GEMM_SMEM>>>(x, Wq, q, BT_, DIN_, DIN_);
    gemm_tf32<<<dim3(G_ * HD_ / 128, BT_ / 128), 128, GEMM_SMEM>>>(x, Wk, k, BT_, G_ * HD_, DIN_);
    gemm_tf32<<<dim3(G_ * HD_ / 128, BT_ / 128), 128, GEMM_SMEM>>>(x, Wv, v, BT_, G_ * HD_, DIN_);

    // norm + rope + kv-cache assembly
    q_norm_rope<<<BT_, H_ * 32>>>(q, qw, cosT, sinT, pid);
    k_norm_rope_scatter<<<BT_, G_ * 32>>>(k, kall, kw, cosT, sinT, pid);
    v_scatter<<<2048, 256>>>(v, vall);
    prev_scatter<<<2048, 256>>>(pk, pv, kall, vall);

    // attention
    attn_kernel<<<dim3(TQ_ / QT, H_, B_), 256, ATTN_SMEM>>>(q, kall, vall, ctx);

    // output projection
    gemm_tf32<<<dim3(DIN_ / 128, BT_ / 128), 128, GEMM_SMEM>>>(ctx, Wo, out, BT_, DIN_, DIN_);

    (void)in_sizes; (void)n_in; (void)out_size;
}

// round 7
// speedup vs baseline: 8.0000x; 1.5502x over previous
#include <cuda_runtime.h>
#include <cuda_bf16.h>
#include <cstdint>

// Problem constants
#define B_    2
#define TQ_   1024
#define DIN_  4096
#define H_    32
#define G_    8
#define HD_   128
#define SPREV 1024
#define SKV   2048          // SPREV + TQ
#define BT_   (B_*TQ_)      // 2048

// ---------------- scratch (no allocation allowed -> __device__ globals) ---------
__device__ float g_q  [(size_t)BT_ * H_ * HD_];   // 2048 x 4096
__device__ float g_k  [(size_t)BT_ * G_ * HD_];   // 2048 x 1024
__device__ float g_v  [(size_t)BT_ * G_ * HD_];   // 2048 x 1024
__device__ float g_ctx[(size_t)BT_ * H_ * HD_];   // 2048 x 4096

// =============================================================================
// shared helpers: cp.async, tf32 convert, mma
// =============================================================================
__device__ __forceinline__ void cp16(void* s, const void* g){
    unsigned sa = (unsigned)__cvta_generic_to_shared(s);
    asm volatile("cp.async.cg.shared.global [%0], [%1], 16;\n" :: "r"(sa), "l"(g));
}
__device__ __forceinline__ void cp_commit(){ asm volatile("cp.async.commit_group;\n" ::); }
template<int NN> __device__ __forceinline__ void cp_wait(){
    asm volatile("cp.async.wait_group %0;\n" :: "n"(NN));
}
__device__ __forceinline__ unsigned f2tf(float x){
    unsigned r; asm("cvt.rna.tf32.f32 %0, %1;" : "=r"(r) : "f"(x)); return r;
}
__device__ __forceinline__ void mma_tf32(float* c, const unsigned* a, const unsigned* b){
    asm volatile(
      "mma.sync.aligned.m16n8k8.row.col.f32.tf32.tf32.f32 "
      "{%0,%1,%2,%3}, {%4,%5,%6,%7}, {%8,%9}, {%0,%1,%2,%3};"
      : "+f"(c[0]), "+f"(c[1]), "+f"(c[2]), "+f"(c[3])
      : "r"(a[0]), "r"(a[1]), "r"(a[2]), "r"(a[3]), "r"(b[0]), "r"(b[1]));
}

// =============================================================================
// tf32 tensor-core NT GEMM: C[m,n] = sum_k A[m,k]*B[n,k]
// Tile 128x128x32, 128 threads (4 warps, each 64x64), double-buffered cp.async.
// =============================================================================
#define GP 36                       // smem pitch (floats)
#define GEMM_SMEM (2 * 128 * GP * 2 * 4)   // 73728 B

__global__ void __launch_bounds__(128) gemm_tf32(const float* __restrict__ A,
                                                 const float* __restrict__ Bm,
                                                 float* __restrict__ C,
                                                 int M, int N, int K)
{
    extern __shared__ float sh[];
    float* As = sh;                  // 2 x [128][GP]
    float* Bs = sh + 2 * 128 * GP;   // 2 x [128][GP]

    const int tid  = threadIdx.x;
    const int lane = tid & 31, warp = tid >> 5;
    const int g  = lane >> 2, tg = lane & 3;
    const int wm = (warp >> 1) * 64, wn = (warp & 1) * 64;

    const float* Ag = A  + (size_t)blockIdx.y * 128 * K;
    const float* Bg = Bm + (size_t)blockIdx.x * 128 * K;

    float c[4][8][4];
    #pragma unroll
    for (int i = 0; i < 4; i++)
        #pragma unroll
        for (int j = 0; j < 8; j++)
            #pragma unroll
            for (int t = 0; t < 4; t++) c[i][j][t] = 0.f;

    const int nkt = K >> 5;

#define STAGE(buf, kt) do {                                                  \
    float* da = As + (buf) * 128 * GP;                                       \
    float* db = Bs + (buf) * 128 * GP;                                       \
    const float* sa = Ag + (size_t)(kt) * 32;                                \
    const float* sb = Bg + (size_t)(kt) * 32;                                \
    _Pragma("unroll")                                                        \
    for (int i = 0; i < 8; i++){                                             \
        int idx = i * 128 + tid; int row = idx >> 3; int c4 = (idx & 7) * 4; \
        cp16(da + row * GP + c4, sa + (size_t)row * K + c4);                 \
        cp16(db + row * GP + c4, sb + (size_t)row * K + c4);                 \
    }                                                                        \
} while (0)

    STAGE(0, 0); cp_commit();

    for (int kt = 0; kt < nkt; kt++) {
        if (kt + 1 < nkt) { STAGE((kt + 1) & 1, kt + 1); cp_commit(); cp_wait<1>(); }
        else              { cp_wait<0>(); }
        __syncthreads();

        const float* Ab = As + (kt & 1) * 128 * GP;
        const float* Bb = Bs + (kt & 1) * 128 * GP;

        #pragma unroll
        for (int ks = 0; ks < 4; ks++) {
            const int kc = ks * 8;
            unsigned a[4][4], bfr[8][2];
            #pragma unroll
            for (int f = 0; f < 4; f++) {
                int ra = wm + f * 16 + g;
                a[f][0] = f2tf(Ab[ra       * GP + kc + tg]);
                a[f][1] = f2tf(Ab[(ra + 8) * GP + kc + tg]);
                a[f][2] = f2tf(Ab[ra       * GP + kc + tg + 4]);
                a[f][3] = f2tf(Ab[(ra + 8) * GP + kc + tg + 4]);
            }
            #pragma unroll
            for (int f = 0; f < 8; f++) {
                int rb = wn + f * 8 + g;
                bfr[f][0] = f2tf(Bb[rb * GP + kc + tg]);
                bfr[f][1] = f2tf(Bb[rb * GP + kc + tg + 4]);
            }
            #pragma unroll
            for (int i = 0; i < 4; i++)
                #pragma unroll
                for (int j = 0; j < 8; j++)
                    mma_tf32(c[i][j], a[i], bfr[j]);
        }
        __syncthreads();
    }
#undef STAGE

    #pragma unroll
    for (int i = 0; i < 4; i++) {
        int row0 = blockIdx.y * 128 + wm + i * 16 + g;
        #pragma unroll
        for (int j = 0; j < 8; j++) {
            int col = blockIdx.x * 128 + wn + j * 8 + 2 * tg;
            *(float2*)(C + (size_t)row0 * N + col)       = make_float2(c[i][j][0], c[i][j][1]);
            *(float2*)(C + (size_t)(row0 + 8) * N + col) = make_float2(c[i][j][2], c[i][j][3]);
        }
    }
}

// =============================================================================
// Per-head RMSNorm + RoPE.  One warp per head; lane l owns dims {l,l+32,l+64,l+96}.
// =============================================================================
__device__ __forceinline__ void norm_rope_head(float* __restrict__ outp,
                                               const float* __restrict__ inp,
                                               const float* __restrict__ w,
                                               const float* __restrict__ cosT,
                                               const float* __restrict__ sinT,
                                               int pos, int l)
{
    float v0 = inp[l], v1 = inp[l + 32], v2 = inp[l + 64], v3 = inp[l + 96];
    float ss = v0 * v0 + v1 * v1 + v2 * v2 + v3 * v3;
    #pragma unroll
    for (int off = 16; off; off >>= 1) ss += __shfl_xor_sync(0xffffffffu, ss, off);
    float rinv = rsqrtf(ss * (1.f / 128.f) + 1e-6f);
    v0 *= rinv * w[l];      v1 *= rinv * w[l + 32];
    v2 *= rinv * w[l + 64]; v3 *= rinv * w[l + 96];
    const float* c = cosT + (size_t)pos * 128;
    const float* s = sinT + (size_t)pos * 128;
    float o0 = v0 * c[l]      - v2 * s[l];
    float o1 = v1 * c[l + 32] - v3 * s[l + 32];
    float o2 = v2 * c[l + 64] + v0 * s[l + 64];
    float o3 = v3 * c[l + 96] + v1 * s[l + 96];
    outp[l] = o0; outp[l + 32] = o1; outp[l + 64] = o2; outp[l + 96] = o3;
}

__global__ void q_norm_rope(float* __restrict__ q, const float* __restrict__ w,
                            const float* __restrict__ cosT, const float* __restrict__ sinT,
                            const int* __restrict__ pid)
{
    int bt = blockIdx.x;
    int h  = threadIdx.x >> 5;
    int l  = threadIdx.x & 31;
    float* base = q + ((size_t)bt * H_ + h) * HD_;
    norm_rope_head(base, base, w, cosT, sinT, pid[bt], l);
}

__global__ void k_norm_rope_scatter(const float* __restrict__ kproj,
                                    float* __restrict__ kall,
                                    const float* __restrict__ w,
                                    const float* __restrict__ cosT,
                                    const float* __restrict__ sinT,
                                    const int* __restrict__ pid)
{
    int bt = blockIdx.x;
    int b = bt >> 10, t = bt & 1023;
    int g = threadIdx.x >> 5;
    int l = threadIdx.x & 31;
    const float* src = kproj + ((size_t)bt * G_ + g) * HD_;
    float* dst = kall + (((size_t)(b * G_ + g) * SKV) + SPREV + t) * HD_;
    norm_rope_head(dst, src, w, cosT, sinT, pid[bt], l);
}

__global__ void v_scatter(const float* __restrict__ vp, float* __restrict__ vall)
{
    size_t i = (size_t)blockIdx.x * blockDim.x + threadIdx.x;  // 524288 float4s
    int d4 = i & 31;
    int g  = (i >> 5) & 7;
    int bt = (int)(i >> 8);
    int b = bt >> 10, t = bt & 1023;
    size_t dst = (((size_t)(b * G_ + g) * SKV) + SPREV + t) * 32 + d4;
    ((float4*)vall)[dst] = ((const float4*)vp)[i];
}

__global__ void prev_scatter(const float* __restrict__ pk, const float* __restrict__ pv,
                             float* __restrict__ kall, float* __restrict__ vall)
{
    size_t i = (size_t)blockIdx.x * blockDim.x + threadIdx.x;  // 524288 float4s
    int d4 = i & 31;
    int s  = (i >> 5) & 1023;
    int bg = (int)(i >> 15);
    size_t dst = ((size_t)bg * SKV + s) * 32 + d4;
    ((float4*)kall)[dst] = ((const float4*)pk)[i];
    ((float4*)vall)[dst] = ((const float4*)pv)[i];
}

// =============================================================================
// Tensor-core flash attention (tf32 mma).
// Block: 256 threads (8 warps) handles (b, h, 128-query tile). KV tile = 64.
// Warp w owns q rows 16w..16w+15. Per tile:
//   S = Q K^T  : m16n8k8, 8 n-tiles x 16 k-steps per warp
//   softmax    : on accumulator fragments (quad shuffles), P -> smem (pitch 68)
//   O += P V   : m16n8k8, 16 n-tiles x 8 k-steps, V read col-wise at pitch 136
// Pitches chosen so every fragment LDS hits 32 distinct banks.
// =============================================================================
#define QP 132
#define KP 132
#define VP 136
#define PP 68
#define ATTN_SMEM ((128*QP + 64*KP + 64*VP + 128*PP) * 4)   // 171008 B

__global__ void __launch_bounds__(256) attn_tc(const float* __restrict__ q,
                                               const float* __restrict__ kall,
                                               const float* __restrict__ vall,
                                               float* __restrict__ ctx)
{
    extern __shared__ float sm[];
    float* Qs = sm;                    // 128 x QP
    float* Ks = Qs + 128 * QP;         // 64 x KP
    float* Vs = Ks + 64 * KP;          // 64 x VP
    float* Ps = Vs + 64 * VP;          // 128 x PP

    const int t0 = blockIdx.x * 128;
    const int h  = blockIdx.y;
    const int b  = blockIdx.z;
    const int gk = h >> 2;             // kv group (H/G = 4)
    const int tid = threadIdx.x;
    const int lane = tid & 31, w = tid >> 5;
    const int g = lane >> 2, tg = lane & 3;

    // load Q tile (rows stride H*HD in gmem)
    const float* qbase = q + ((size_t)(b * TQ_ + t0) * H_ + h) * HD_;
    #pragma unroll 4
    for (int i = tid; i < 128 * 32; i += 256) {
        int row = i >> 5, c4 = (i & 31) * 4;
        *(float4*)(Qs + row * QP + c4) =
            *(const float4*)(qbase + (size_t)row * (H_ * HD_) + c4);
    }

    const int row0 = 16 * w + g;                 // first q row of this thread
    const int qp0 = SPREV + t0 + row0;
    const int qp1 = qp0 + 8;
    const int kv_lim = SPREV + t0 + 128;
    const float scale = 0.08838834764831845f;    // 1/sqrt(128)

    const float* kb = kall + (size_t)(b * G_ + gk) * SKV * HD_;
    const float* vb = vall + (size_t)(b * G_ + gk) * SKV * HD_;

    float oacc[16][4];
    #pragma unroll
    for (int j = 0; j < 16; j++)
        #pragma unroll
        for (int t = 0; t < 4; t++) oacc[j][t] = 0.f;
    float m0 = -1e30f, m1 = -1e30f, l0 = 0.f, l1 = 0.f;

    __syncthreads();

    for (int j0 = 0; j0 < kv_lim; j0 += 64) {
        // ---- load K, V tiles ----
        #pragma unroll 4
        for (int i = tid; i < 64 * 32; i += 256) {
            int row = i >> 5, c4 = (i & 31) * 4;
            *(float4*)(Ks + row * KP + c4) =
                *(const float4*)(kb + (size_t)(j0 + row) * HD_ + c4);
            *(float4*)(Vs + row * VP + c4) =
                *(const float4*)(vb + (size_t)(j0 + row) * HD_ + c4);
        }
        __syncthreads();

        // ---- scores S = Q K^T ----
        float sacc[8][4];
        #pragma unroll
        for (int j = 0; j < 8; j++)
            #pragma unroll
            for (int t = 0; t < 4; t++) sacc[j][t] = 0.f;

        #pragma unroll
        for (int ks = 0; ks < 16; ks++) {
            const int kc = ks * 8;
            unsigned a[4];
            a[0] = f2tf(Qs[row0       * QP + kc + tg]);
            a[1] = f2tf(Qs[(row0 + 8) * QP + kc + tg]);
            a[2] = f2tf(Qs[row0       * QP + kc + tg + 4]);
            a[3] = f2tf(Qs[(row0 + 8) * QP + kc + tg + 4]);
            #pragma unroll
            for (int j = 0; j < 8; j++) {
                unsigned bfr[2];
                bfr[0] = f2tf(Ks[(8 * j + g) * KP + kc + tg]);
                bfr[1] = f2tf(Ks[(8 * j + g) * KP + kc + tg + 4]);
                mma_tf32(sacc[j], a, bfr);
            }
        }

        // ---- softmax on fragments ----
        const bool nm = (j0 + 63 > SPREV + t0);  // any masked element in tile?
        float ml0 = -1e30f, ml1 = -1e30f;
        #pragma unroll
        for (int j = 0; j < 8; j++) {
            if (nm) {
                int c0 = j0 + 8 * j + 2 * tg, c1 = c0 + 1;
                sacc[j][0] = (c0 <= qp0) ? sacc[j][0] * scale : -1e30f;
                sacc[j][1] = (c1 <= qp0) ? sacc[j][1] * scale : -1e30f;
                sacc[j][2] = (c0 <= qp1) ? sacc[j][2] * scale : -1e30f;
                sacc[j][3] = (c1 <= qp1) ? sacc[j][3] * scale : -1e30f;
            } else {
                sacc[j][0] *= scale; sacc[j][1] *= scale;
                sacc[j][2] *= scale; sacc[j][3] *= scale;
            }
            ml0 = fmaxf(ml0, fmaxf(sacc[j][0], sacc[j][1]));
            ml1 = fmaxf(ml1, fmaxf(sacc[j][2], sacc[j][3]));
        }
        ml0 = fmaxf(ml0, __shfl_xor_sync(0xffffffffu, ml0, 1));
        ml0 = fmaxf(ml0, __shfl_xor_sync(0xffffffffu, ml0, 2));
        ml1 = fmaxf(ml1, __shfl_xor_sync(0xffffffffu, ml1, 1));
        ml1 = fmaxf(ml1, __shfl_xor_sync(0xffffffffu, ml1, 2));
        float mn0 = fmaxf(m0, ml0), mn1 = fmaxf(m1, ml1);
        float al0 = __expf(m0 - mn0), al1 = __expf(m1 - mn1);

        float ls0 = 0.f, ls1 = 0.f;
        #pragma unroll
        for (int j = 0; j < 8; j++) {
            float p00 = __expf(sacc[j][0] - mn0);
            float p01 = __expf(sacc[j][1] - mn0);
            float p10 = __expf(sacc[j][2] - mn1);
            float p11 = __expf(sacc[j][3] - mn1);
            ls0 += p00 + p01; ls1 += p10 + p11;
            *(float2*)(Ps + row0       * PP + 8 * j + 2 * tg) = make_float2(p00, p01);
            *(float2*)(Ps + (row0 + 8) * PP + 8 * j + 2 * tg) = make_float2(p10, p11);
        }
        ls0 += __shfl_xor_sync(0xffffffffu, ls0, 1);
        ls0 += __shfl_xor_sync(0xffffffffu, ls0, 2);
        ls1 += __shfl_xor_sync(0xffffffffu, ls1, 1);
        ls1 += __shfl_xor_sync(0xffffffffu, ls1, 2);
        l0 = l0 * al0 + ls0;  m0 = mn0;
        l1 = l1 * al1 + ls1;  m1 = mn1;

        #pragma unroll
        for (int j = 0; j < 16; j++) {
            oacc[j][0] *= al0; oacc[j][1] *= al0;
            oacc[j][2] *= al1; oacc[j][3] *= al1;
        }
        __syncwarp();   // P rows of this warp: cross-lane STS->LDS visibility

        // ---- O += P V ----
        #pragma unroll
        for (int ks = 0; ks < 8; ks++) {
            const int kc = ks * 8;
            unsigned a[4];
            a[0] = f2tf(Ps[row0       * PP + kc + tg]);
            a[1] = f2tf(Ps[(row0 + 8) * PP + kc + tg]);
            a[2] = f2tf(Ps[row0       * PP + kc + tg + 4]);
            a[3] = f2tf(Ps[(row0 + 8) * PP + kc + tg + 4]);
            #pragma unroll
            for (int j = 0; j < 16; j++) {
                unsigned bfr[2];
                bfr[0] = f2tf(Vs[(kc + tg)     * VP + 8 * j + g]);
                bfr[1] = f2tf(Vs[(kc + tg + 4) * VP + 8 * j + g]);
                mma_tf32(oacc[j], a, bfr);
            }
        }
        __syncthreads();   // protect Ks/Vs/Ps before next tile load
    }

    // ---- epilogue ----
    float i0 = 1.f / l0, i1 = 1.f / l1;
    float* c0p = ctx + ((size_t)(b * TQ_ + t0 + row0)     * H_ + h) * HD_;
    float* c1p = ctx + ((size_t)(b * TQ_ + t0 + row0 + 8) * H_ + h) * HD_;
    #pragma unroll
    for (int j = 0; j < 16; j++) {
        int col = 8 * j + 2 * tg;
        *(float2*)(c0p + col) = make_float2(oacc[j][0] * i0, oacc[j][1] * i0);
        *(float2*)(c1p + col) = make_float2(oacc[j][2] * i1, oacc[j][3] * i1);
    }
}

// =============================================================================
// host launcher
// =============================================================================
static float* sym_addr(const void* symbol)
{
    void* p = nullptr;
    cudaGetSymbolAddress(&p, symbol);
    return (float*)p;
}

extern "C" void kernel_launch(void* const* d_in, const int* in_sizes, int n_in,
                              void* d_out, int out_size)
{
    const float* x    = (const float*)d_in[0];
    const float* Wq   = (const float*)d_in[1];
    const float* Wk   = (const float*)d_in[2];
    const float* Wv   = (const float*)d_in[3];
    const float* Wo   = (const float*)d_in[4];
    const float* qw   = (const float*)d_in[5];
    const float* kw   = (const float*)d_in[6];
    const float* cosT = (const float*)d_in[7];
    const float* sinT = (const float*)d_in[8];
    const float* pk   = (const float*)d_in[9];
    const float* pv   = (const float*)d_in[10];
    const int*   pid  = (const int*)d_in[11];
    // d_in[12] = mask, computed analytically

    float* out  = (float*)d_out;                                    // B*T*DIN
    float* kall = out  + (size_t)B_ * TQ_ * DIN_;                   // B*G*SKV*HD
    float* vall = kall + (size_t)B_ * G_ * SKV * HD_;

    float* q   = sym_addr(g_q);
    float* k   = sym_addr(g_k);
    float* v   = sym_addr(g_v);
    float* ctx = sym_addr(g_ctx);

    cudaFuncSetAttribute(gemm_tf32, cudaFuncAttributeMaxDynamicSharedMemorySize, GEMM_SMEM);
    cudaFuncSetAttribute(attn_tc, cudaFuncAttributeMaxDynamicSharedMemorySize, ATTN_SMEM);

    // QKV projections (tf32 tensor-core NT gemms)
    gemm_tf32<<<dim3(DIN_ / 128, BT_ / 128), 128, GEMM_SMEM>>>(x, Wq, q, BT_, DIN_, DIN_);
    gemm_tf32<<<dim3(G_ * HD_ / 128, BT_ / 128), 128, GEMM_SMEM>>>(x, Wk, k, BT_, G_ * HD_, DIN_);
    gemm_tf32<<<dim3(G_ * HD_ / 128, BT_ / 128), 128, GEMM_SMEM>>>(x, Wv, v, BT_, G_ * HD_, DIN_);

    // norm + rope + kv-cache assembly
    q_norm_rope<<<BT_, H_ * 32>>>(q, qw, cosT, sinT, pid);
    k_norm_rope_scatter<<<BT_, G_ * 32>>>(k, kall, kw, cosT, sinT, pid);
    v_scatter<<<2048, 256>>>(v, vall);
    prev_scatter<<<2048, 256>>>(pk, pv, kall, vall);

    // tensor-core attention
    attn_tc<<<dim3(TQ_ / 128, H_, B_), 256, ATTN_SMEM>>>(q, kall, vall, ctx);

    // output projection
    gemm_tf32<<<dim3(DIN_ / 128, BT_ / 128), 128, GEMM_SMEM>>>(ctx, Wo, out, BT_, DIN_, DIN_);

    (void)in_sizes; (void)n_in; (void)out_size;
}

// round 9
// speedup vs baseline: 10.1266x; 1.2658x over previous
#include <cuda_runtime.h>
#include <cuda_bf16.h>
#include <cstdint>

// Problem constants
#define B_    2
#define TQ_   1024
#define DIN_  4096
#define H_    32
#define G_    8
#define HD_   128
#define SPREV 1024
#define SKV   2048          // SPREV + TQ
#define BT_   (B_*TQ_)      // 2048
#define NQKV  6144          // H*HD + 2*G*HD

// ---------------- scratch (no allocation allowed -> __device__ globals) ---------
__device__ float g_qkv [(size_t)BT_ * NQKV];        // fused q|k|v projections
__device__ float g_ctx [(size_t)BT_ * H_ * HD_];    // 2048 x 4096 (tf32-rounded)
__device__ float g_xr  [(size_t)BT_ * DIN_];        // tf32-rounded x
__device__ float g_wqkvr[(size_t)NQKV * DIN_];      // tf32-rounded [Wq;Wk;Wv]
__device__ float g_wor [(size_t)DIN_ * H_ * HD_];   // tf32-rounded Wo

// =============================================================================
// helpers
// =============================================================================
__device__ __forceinline__ void cp16(void* s, const void* g){
    unsigned sa = (unsigned)__cvta_generic_to_shared(s);
    asm volatile("cp.async.cg.shared.global [%0], [%1], 16;\n" :: "r"(sa), "l"(g));
}
__device__ __forceinline__ void cp_commit(){ asm volatile("cp.async.commit_group;\n" ::); }
template<int NN> __device__ __forceinline__ void cp_wait(){
    asm volatile("cp.async.wait_group %0;\n" :: "n"(NN));
}
__device__ __forceinline__ unsigned f2tf(float x){
    unsigned r; asm("cvt.rna.tf32.f32 %0, %1;" : "=r"(r) : "f"(x)); return r;
}
__device__ __forceinline__ float f2tff(float x){ return __uint_as_float(f2tf(x)); }
__device__ __forceinline__ void mma_tf32(float* c, const unsigned* a, const unsigned* b){
    asm volatile(
      "mma.sync.aligned.m16n8k8.row.col.f32.tf32.tf32.f32 "
      "{%0,%1,%2,%3}, {%4,%5,%6,%7}, {%8,%9}, {%0,%1,%2,%3};"
      : "+f"(c[0]), "+f"(c[1]), "+f"(c[2]), "+f"(c[3])
      : "r"(a[0]), "r"(a[1]), "r"(a[2]), "r"(a[3]), "r"(b[0]), "r"(b[1]));
}

// =============================================================================
// tf32 rounding copy (inputs are pre-rounded once; inner loops use raw bits)
// =============================================================================
__global__ void round_copy(const float4* __restrict__ s, float4* __restrict__ d, int n4)
{
    int i = blockIdx.x * 256 + threadIdx.x;
    if (i >= n4) return;
    float4 v = s[i];
    v.x = f2tff(v.x); v.y = f2tff(v.y); v.z = f2tff(v.z); v.w = f2tff(v.w);
    d[i] = v;
}

// =============================================================================
// tf32 tensor-core NT GEMM: C[m,n] = sum_k A[m,k]*B[n,k]
// Tile 128x128x32, 128 threads (4 warps, each 64x64), double-buffered cp.async.
// A and B MUST be pre-rounded to tf32 (raw-bit fragment loads, no CVT in loop).
// =============================================================================
#define GP 36                       // smem pitch (floats)
#define GEMM_SMEM (2 * 128 * GP * 2 * 4)   // 73728 B

__global__ void __launch_bounds__(128) gemm_tf32(const float* __restrict__ A,
                                                 const float* __restrict__ Bm,
                                                 float* __restrict__ C,
                                                 int M, int N, int K)
{
    extern __shared__ float sh[];
    float* As = sh;                  // 2 x [128][GP]
    float* Bs = sh + 2 * 128 * GP;   // 2 x [128][GP]

    const int tid  = threadIdx.x;
    const int lane = tid & 31, warp = tid >> 5;
    const int g  = lane >> 2, tg = lane & 3;
    const int wm = (warp >> 1) * 64, wn = (warp & 1) * 64;

    const float* Ag = A  + (size_t)blockIdx.y * 128 * K;
    const float* Bg = Bm + (size_t)blockIdx.x * 128 * K;

    float c[4][8][4];
    #pragma unroll
    for (int i = 0; i < 4; i++)
        #pragma unroll
        for (int j = 0; j < 8; j++)
            #pragma unroll
            for (int t = 0; t < 4; t++) c[i][j][t] = 0.f;

    const int nkt = K >> 5;

#define STAGE(buf, kt) do {                                                  \
    float* da = As + (buf) * 128 * GP;                                       \
    float* db = Bs + (buf) * 128 * GP;                                       \
    const float* sa = Ag + (size_t)(kt) * 32;                                \
    const float* sb = Bg + (size_t)(kt) * 32;                                \
    _Pragma("unroll")                                                        \
    for (int i = 0; i < 8; i++){                                             \
        int idx = i * 128 + tid; int row = idx >> 3; int c4 = (idx & 7) * 4; \
        cp16(da + row * GP + c4, sa + (size_t)row * K + c4);                 \
        cp16(db + row * GP + c4, sb + (size_t)row * K + c4);                 \
    }                                                                        \
} while (0)

    STAGE(0, 0); cp_commit();

    for (int kt = 0; kt < nkt; kt++) {
        if (kt + 1 < nkt) { STAGE((kt + 1) & 1, kt + 1); cp_commit(); cp_wait<1>(); }
        else              { cp_wait<0>(); }
        __syncthreads();

        const float* Ab = As + (kt & 1) * 128 * GP;
        const float* Bb = Bs + (kt & 1) * 128 * GP;

        #pragma unroll
        for (int ks = 0; ks < 4; ks++) {
            const int kc = ks * 8;
            unsigned a[4][4], bfr[8][2];
            #pragma unroll
            for (int f = 0; f < 4; f++) {
                int ra = wm + f * 16 + g;
                a[f][0] = __float_as_uint(Ab[ra       * GP + kc + tg]);
                a[f][1] = __float_as_uint(Ab[(ra + 8) * GP + kc + tg]);
                a[f][2] = __float_as_uint(Ab[ra       * GP + kc + tg + 4]);
                a[f][3] = __float_as_uint(Ab[(ra + 8) * GP + kc + tg + 4]);
            }
            #pragma unroll
            for (int f = 0; f < 8; f++) {
                int rb = wn + f * 8 + g;
                bfr[f][0] = __float_as_uint(Bb[rb * GP + kc + tg]);
                bfr[f][1] = __float_as_uint(Bb[rb * GP + kc + tg + 4]);
            }
            #pragma unroll
            for (int i = 0; i < 4; i++)
                #pragma unroll
                for (int j = 0; j < 8; j++)
                    mma_tf32(c[i][j], a[i], bfr[j]);
        }
        __syncthreads();
    }
#undef STAGE

    #pragma unroll
    for (int i = 0; i < 4; i++) {
        int row0 = blockIdx.y * 128 + wm + i * 16 + g;
        #pragma unroll
        for (int j = 0; j < 8; j++) {
            int col = blockIdx.x * 128 + wn + j * 8 + 2 * tg;
            *(float2*)(C + (size_t)row0 * N + col)       = make_float2(c[i][j][0], c[i][j][1]);
            *(float2*)(C + (size_t)(row0 + 8) * N + col) = make_float2(c[i][j][2], c[i][j][3]);
        }
    }
}

// =============================================================================
// Per-head RMSNorm + RoPE.  One warp per head; lane l owns dims {l,l+32,l+64,l+96}.
// =============================================================================
template<bool ROUND>
__device__ __forceinline__ void norm_rope_head(float* __restrict__ outp,
                                               const float* __restrict__ inp,
                                               const float* __restrict__ w,
                                               const float* __restrict__ cosT,
                                               const float* __restrict__ sinT,
                                               int pos, int l)
{
    float v0 = inp[l], v1 = inp[l + 32], v2 = inp[l + 64], v3 = inp[l + 96];
    float ss = v0 * v0 + v1 * v1 + v2 * v2 + v3 * v3;
    #pragma unroll
    for (int off = 16; off; off >>= 1) ss += __shfl_xor_sync(0xffffffffu, ss, off);
    float rinv = rsqrtf(ss * (1.f / 128.f) + 1e-6f);
    v0 *= rinv * w[l];      v1 *= rinv * w[l + 32];
    v2 *= rinv * w[l + 64]; v3 *= rinv * w[l + 96];
    const float* c = cosT + (size_t)pos * 128;
    const float* s = sinT + (size_t)pos * 128;
    float o0 = v0 * c[l]      - v2 * s[l];
    float o1 = v1 * c[l + 32] - v3 * s[l + 32];
    float o2 = v2 * c[l + 64] + v0 * s[l + 64];
    float o3 = v3 * c[l + 96] + v1 * s[l + 96];
    if (ROUND) { o0 = f2tff(o0); o1 = f2tff(o1); o2 = f2tff(o2); o3 = f2tff(o3); }
    outp[l] = o0; outp[l + 32] = o1; outp[l + 64] = o2; outp[l + 96] = o3;
}

// Q lives in the fused qkv buffer (row stride NQKV). Output rounded to tf32
// (consumed only by attention).
__global__ void q_norm_rope(float* __restrict__ qkv, const float* __restrict__ w,
                            const float* __restrict__ cosT, const float* __restrict__ sinT,
                            const int* __restrict__ pid)
{
    int bt = blockIdx.x;
    int h  = threadIdx.x >> 5;
    int l  = threadIdx.x & 31;
    float* base = qkv + (size_t)bt * NQKV + h * HD_;
    norm_rope_head<true>(base, base, w, cosT, sinT, pid[bt], l);
}

// K in qkv cols [4096, 5120); exact fp32 result into kall (it is an output).
__global__ void k_norm_rope_scatter(const float* __restrict__ qkv,
                                    float* __restrict__ kall,
                                    const float* __restrict__ w,
                                    const float* __restrict__ cosT,
                                    const float* __restrict__ sinT,
                                    const int* __restrict__ pid)
{
    int bt = blockIdx.x;
    int b = bt >> 10, t = bt & 1023;
    int g = threadIdx.x >> 5;
    int l = threadIdx.x & 31;
    const float* src = qkv + (size_t)bt * NQKV + H_ * HD_ + g * HD_;
    float* dst = kall + (((size_t)(b * G_ + g) * SKV) + SPREV + t) * HD_;
    norm_rope_head<false>(dst, src, w, cosT, sinT, pid[bt], l);
}

// V in qkv cols [5120, 6144) -> v_all [b,g,SPREV+t,d]
__global__ void v_scatter(const float* __restrict__ qkv, float* __restrict__ vall)
{
    size_t i = (size_t)blockIdx.x * blockDim.x + threadIdx.x;  // 524288 float4s
    int d4 = i & 31;
    int g  = (i >> 5) & 7;
    int bt = (int)(i >> 8);
    int b = bt >> 10, t = bt & 1023;
    size_t src = (size_t)bt * (NQKV / 4) + (H_ * HD_ + G_ * HD_) / 4 + g * 32 + d4;
    size_t dst = (((size_t)(b * G_ + g) * SKV) + SPREV + t) * 32 + d4;
    ((float4*)vall)[dst] = ((const float4*)qkv)[src];
}

__global__ void prev_scatter(const float* __restrict__ pk, const float* __restrict__ pv,
                             float* __restrict__ kall, float* __restrict__ vall)
{
    size_t i = (size_t)blockIdx.x * blockDim.x + threadIdx.x;  // 524288 float4s
    int d4 = i & 31;
    int s  = (i >> 5) & 1023;
    int bg = (int)(i >> 15);
    size_t dst = ((size_t)bg * SKV + s) * 32 + d4;
    ((float4*)kall)[dst] = ((const float4*)pk)[i];
    ((float4*)vall)[dst] = ((const float4*)pv)[i];
}

// =============================================================================
// Tensor-core flash attention (tf32 mma.sync).
// All smem tiles hold tf32-rounded values (rounded at store); fragment loads
// are raw bits — no CVT in the mma loops.
// =============================================================================
#define QP 132
#define KP 132
#define VP 136
#define PP 68
#define ATTN_SMEM ((128*QP + 64*KP + 64*VP + 128*PP) * 4)   // 171008 B

__global__ void __launch_bounds__(256) attn_tc(const float* __restrict__ q,
                                               const float* __restrict__ kall,
                                               const float* __restrict__ vall,
                                               float* __restrict__ ctx)
{
    extern __shared__ float sm[];
    float* Qs = sm;                    // 128 x QP
    float* Ks = Qs + 128 * QP;         // 64 x KP
    float* Vs = Ks + 64 * KP;          // 64 x VP
    float* Ps = Vs + 64 * VP;          // 128 x PP

    const int t0 = blockIdx.x * 128;
    const int h  = blockIdx.y;
    const int b  = blockIdx.z;
    const int gk = h >> 2;             // kv group (H/G = 4)
    const int tid = threadIdx.x;
    const int lane = tid & 31, w = tid >> 5;
    const int g = lane >> 2, tg = lane & 3;

    // Q tile: already tf32-rounded by q_norm_rope (row stride NQKV)
    const float* qbase = q + (size_t)(b * TQ_ + t0) * NQKV + h * HD_;
    #pragma unroll 4
    for (int i = tid; i < 128 * 32; i += 256) {
        int row = i >> 5, c4 = (i & 31) * 4;
        *(float4*)(Qs + row * QP + c4) =
            *(const float4*)(qbase + (size_t)row * NQKV + c4);
    }

    const int row0 = 16 * w + g;
    const int qp0 = SPREV + t0 + row0;
    const int qp1 = qp0 + 8;
    const int kv_lim = SPREV + t0 + 128;
    const float scale = 0.08838834764831845f;    // 1/sqrt(128)

    const float* kb = kall + (size_t)(b * G_ + gk) * SKV * HD_;
    const float* vb = vall + (size_t)(b * G_ + gk) * SKV * HD_;

    float oacc[16][4];
    #pragma unroll
    for (int j = 0; j < 16; j++)
        #pragma unroll
        for (int t = 0; t < 4; t++) oacc[j][t] = 0.f;
    float m0 = -1e30f, m1 = -1e30f, l0 = 0.f, l1 = 0.f;

    __syncthreads();

    for (int j0 = 0; j0 < kv_lim; j0 += 64) {
        // load K,V tiles; round to tf32 at store (K/V in gmem are exact outputs)
        #pragma unroll 4
        for (int i = tid; i < 64 * 32; i += 256) {
            int row = i >> 5, c4 = (i & 31) * 4;
            float4 kv4 = *(const float4*)(kb + (size_t)(j0 + row) * HD_ + c4);
            kv4.x = f2tff(kv4.x); kv4.y = f2tff(kv4.y);
            kv4.z = f2tff(kv4.z); kv4.w = f2tff(kv4.w);
            *(float4*)(Ks + row * KP + c4) = kv4;
            float4 vv4 = *(const float4*)(vb + (size_t)(j0 + row) * HD_ + c4);
            vv4.x = f2tff(vv4.x); vv4.y = f2tff(vv4.y);
            vv4.z = f2tff(vv4.z); vv4.w = f2tff(vv4.w);
            *(float4*)(Vs + row * VP + c4) = vv4;
        }
        __syncthreads();

        // ---- scores S = Q K^T (raw-bit fragments) ----
        float sacc[8][4];
        #pragma unroll
        for (int j = 0; j < 8; j++)
            #pragma unroll
            for (int t = 0; t < 4; t++) sacc[j][t] = 0.f;

        #pragma unroll
        for (int ks = 0; ks < 16; ks++) {
            const int kc = ks * 8;
            unsigned a[4];
            a[0] = __float_as_uint(Qs[row0       * QP + kc + tg]);
            a[1] = __float_as_uint(Qs[(row0 + 8) * QP + kc + tg]);
            a[2] = __float_as_uint(Qs[row0       * QP + kc + tg + 4]);
            a[3] = __float_as_uint(Qs[(row0 + 8) * QP + kc + tg + 4]);
            #pragma unroll
            for (int j = 0; j < 8; j++) {
                unsigned bfr[2];
                bfr[0] = __float_as_uint(Ks[(8 * j + g) * KP + kc + tg]);
                bfr[1] = __float_as_uint(Ks[(8 * j + g) * KP + kc + tg + 4]);
                mma_tf32(sacc[j], a, bfr);
            }
        }

        const bool nm = (j0 + 63 > SPREV + t0);
        float ml0 = -1e30f, ml1 = -1e30f;
        #pragma unroll
        for (int j = 0; j < 8; j++) {
            if (nm) {
                int c0 = j0 + 8 * j + 2 * tg, c1 = c0 + 1;
                sacc[j][0] = (c0 <= qp0) ? sacc[j][0] * scale : -1e30f;
                sacc[j][1] = (c1 <= qp0) ? sacc[j][1] * scale : -1e30f;
                sacc[j][2] = (c0 <= qp1) ? sacc[j][2] * scale : -1e30f;
                sacc[j][3] = (c1 <= qp1) ? sacc[j][3] * scale : -1e30f;
            } else {
                sacc[j][0] *= scale; sacc[j][1] *= scale;
                sacc[j][2] *= scale; sacc[j][3] *= scale;
            }
            ml0 = fmaxf(ml0, fmaxf(sacc[j][0], sacc[j][1]));
            ml1 = fmaxf(ml1, fmaxf(sacc[j][2], sacc[j][3]));
        }
        ml0 = fmaxf(ml0, __shfl_xor_sync(0xffffffffu, ml0, 1));
        ml0 = fmaxf(ml0, __shfl_xor_sync(0xffffffffu, ml0, 2));
        ml1 = fmaxf(ml1, __shfl_xor_sync(0xffffffffu, ml1, 1));
        ml1 = fmaxf(ml1, __shfl_xor_sync(0xffffffffu, ml1, 2));
        float mn0 = fmaxf(m0, ml0), mn1 = fmaxf(m1, ml1);
        float al0 = __expf(m0 - mn0), al1 = __expf(m1 - mn1);

        float ls0 = 0.f, ls1 = 0.f;
        #pragma unroll
        for (int j = 0; j < 8; j++) {
            float p00 = __expf(sacc[j][0] - mn0);
            float p01 = __expf(sacc[j][1] - mn0);
            float p10 = __expf(sacc[j][2] - mn1);
            float p11 = __expf(sacc[j][3] - mn1);
            ls0 += p00 + p01; ls1 += p10 + p11;
            // store tf32-rounded P (numerics identical to cvt-at-load scheme)
            *(float2*)(Ps + row0       * PP + 8 * j + 2 * tg) =
                make_float2(f2tff(p00), f2tff(p01));
            *(float2*)(Ps + (row0 + 8) * PP + 8 * j + 2 * tg) =
                make_float2(f2tff(p10), f2tff(p11));
        }
        ls0 += __shfl_xor_sync(0xffffffffu, ls0, 1);
        ls0 += __shfl_xor_sync(0xffffffffu, ls0, 2);
        ls1 += __shfl_xor_sync(0xffffffffu, ls1, 1);
        ls1 += __shfl_xor_sync(0xffffffffu, ls1, 2);
        l0 = l0 * al0 + ls0;  m0 = mn0;
        l1 = l1 * al1 + ls1;  m1 = mn1;

        #pragma unroll
        for (int j = 0; j < 16; j++) {
            oacc[j][0] *= al0; oacc[j][1] *= al0;
            oacc[j][2] *= al1; oacc[j][3] *= al1;
        }
        __syncwarp();

        // ---- O += P V (raw-bit fragments) ----
        #pragma unroll
        for (int ks = 0; ks < 8; ks++) {
            const int kc = ks * 8;
            unsigned a[4];
            a[0] = __float_as_uint(Ps[row0       * PP + kc + tg]);
            a[1] = __float_as_uint(Ps[(row0 + 8) * PP + kc + tg]);
            a[2] = __float_as_uint(Ps[row0       * PP + kc + tg + 4]);
            a[3] = __float_as_uint(Ps[(row0 + 8) * PP + kc + tg + 4]);
            #pragma unroll
            for (int j = 0; j < 16; j++) {
                unsigned bfr[2];
                bfr[0] = __float_as_uint(Vs[(kc + tg)     * VP + 8 * j + g]);
                bfr[1] = __float_as_uint(Vs[(kc + tg + 4) * VP + 8 * j + g]);
                mma_tf32(oacc[j], a, bfr);
            }
        }
        __syncthreads();
    }

    // epilogue: write ctx pre-rounded to tf32 (feeds out-projection A operand)
    float i0 = 1.f / l0, i1 = 1.f / l1;
    float* c0p = ctx + ((size_t)(b * TQ_ + t0 + row0)     * H_ + h) * HD_;
    float* c1p = ctx + ((size_t)(b * TQ_ + t0 + row0 + 8) * H_ + h) * HD_;
    #pragma unroll
    for (int j = 0; j < 16; j++) {
        int col = 8 * j + 2 * tg;
        *(float2*)(c0p + col) = make_float2(f2tff(oacc[j][0] * i0), f2tff(oacc[j][1] * i0));
        *(float2*)(c1p + col) = make_float2(f2tff(oacc[j][2] * i1), f2tff(oacc[j][3] * i1));
    }
}

// =============================================================================
// host launcher
// =============================================================================
static float* sym_addr(const void* symbol)
{
    void* p = nullptr;
    cudaGetSymbolAddress(&p, symbol);
    return (float*)p;
}

extern "C" void kernel_launch(void* const* d_in, const int* in_sizes, int n_in,
                              void* d_out, int out_size)
{
    const float* x    = (const float*)d_in[0];
    const float* Wq   = (const float*)d_in[1];
    const float* Wk   = (const float*)d_in[2];
    const float* Wv   = (const float*)d_in[3];
    const float* Wo   = (const float*)d_in[4];
    const float* qw   = (const float*)d_in[5];
    const float* kw   = (const float*)d_in[6];
    const float* cosT = (const float*)d_in[7];
    const float* sinT = (const float*)d_in[8];
    const float* pk   = (const float*)d_in[9];
    const float* pv   = (const float*)d_in[10];
    const int*   pid  = (const int*)d_in[11];
    // d_in[12] = mask, computed analytically

    float* out  = (float*)d_out;                                    // B*T*DIN
    float* kall = out  + (size_t)B_ * TQ_ * DIN_;                   // B*G*SKV*HD
    float* vall = kall + (size_t)B_ * G_ * SKV * HD_;

    float* qkv  = sym_addr(g_qkv);
    float* ctx  = sym_addr(g_ctx);
    float* xr   = sym_addr(g_xr);
    float* wqkv = sym_addr(g_wqkvr);
    float* wor  = sym_addr(g_wor);

    cudaFuncSetAttribute(gemm_tf32, cudaFuncAttributeMaxDynamicSharedMemorySize, GEMM_SMEM);
    cudaFuncSetAttribute(attn_tc,   cudaFuncAttributeMaxDynamicSharedMemorySize, ATTN_SMEM);

    // 1-5) tf32 rounding pre-pass (5 launches -> gemm_qkv lands in ncu's -s 5 window)
    round_copy<<< 8192, 256>>>((const float4*)x,  (float4*)xr,                       2097152);
    round_copy<<<16384, 256>>>((const float4*)Wq, (float4*)wqkv,                     4194304);
    round_copy<<< 4096, 256>>>((const float4*)Wk, (float4*)(wqkv + 16777216),        1048576);
    round_copy<<< 4096, 256>>>((const float4*)Wv, (float4*)(wqkv + 20971520),        1048576);
    round_copy<<<16384, 256>>>((const float4*)Wo, (float4*)wor,                      4194304);

    // 6) fused QKV projection: [2048 x 6144] = xr @ [Wq;Wk;Wv]^T
    gemm_tf32<<<dim3(NQKV / 128, BT_ / 128), 128, GEMM_SMEM>>>(xr, wqkv, qkv, BT_, NQKV, DIN_);

    // 7) prev kv cache copy
    prev_scatter<<<2048, 256>>>(pk, pv, kall, vall);

    // 8-10) norm + rope + kv assembly
    q_norm_rope<<<BT_, H_ * 32>>>(qkv, qw, cosT, sinT, pid);
    k_norm_rope_scatter<<<BT_, G_ * 32>>>(qkv, kall, kw, cosT, sinT, pid);
    v_scatter<<<2048, 256>>>(qkv, vall);

    // 11) attention
    attn_tc<<<dim3(TQ_ / 128, H_, B_), 256, ATTN_SMEM>>>(qkv, kall, vall, ctx);

    // 12) output projection
    gemm_tf32<<<dim3(DIN_ / 128, BT_ / 128), 128, GEMM_SMEM>>>(ctx, wor, out, BT_, DIN_, DIN_);

    (void)in_sizes; (void)n_in; (void)out_size;
}

// round 10
// speedup vs baseline: 15.9103x; 1.5711x over previous
#include <cuda_runtime.h>
#include <cuda_bf16.h>
#include <cuda_fp16.h>
#include <cstdint>

// Problem constants
#define B_    2
#define TQ_   1024
#define DIN_  4096
#define H_    32
#define G_    8
#define HD_   128
#define SPREV 1024
#define SKV   2048          // SPREV + TQ
#define BT_   (B_*TQ_)      // 2048
#define NQKV  6144          // H*HD + 2*G*HD

// ---------------- scratch (no allocation allowed -> __device__ globals) ---------
__device__ float  g_qkv [(size_t)BT_ * NQKV];        // fused q|k|v projections (fp32)
__device__ __half g_xh  [(size_t)BT_ * DIN_];        // fp16 x
__device__ __half g_wqkvh[(size_t)NQKV * DIN_];      // fp16 [Wq;Wk;Wv]
__device__ __half g_woh [(size_t)DIN_ * H_ * HD_];   // fp16 Wo
__device__ __half g_qh  [(size_t)BT_ * H_ * HD_];    // fp16 Q (post norm+rope)
__device__ __half g_ctxh[(size_t)BT_ * H_ * HD_];    // fp16 attention output

// =============================================================================
// helpers
// =============================================================================
__device__ __forceinline__ void cp16(void* s, const void* g){
    unsigned sa = (unsigned)__cvta_generic_to_shared(s);
    asm volatile("cp.async.cg.shared.global [%0], [%1], 16;\n" :: "r"(sa), "l"(g));
}
__device__ __forceinline__ void cp_commit(){ asm volatile("cp.async.commit_group;\n" ::); }
template<int NN> __device__ __forceinline__ void cp_wait(){
    asm volatile("cp.async.wait_group %0;\n" :: "n"(NN));
}
__device__ __forceinline__ unsigned f2tf(float x){
    unsigned r; asm("cvt.rna.tf32.f32 %0, %1;" : "=r"(r) : "f"(x)); return r;
}
__device__ __forceinline__ float f2tff(float x){ return __uint_as_float(f2tf(x)); }
__device__ __forceinline__ void mma_tf32(float* c, const unsigned* a, const unsigned* b){
    asm volatile(
      "mma.sync.aligned.m16n8k8.row.col.f32.tf32.tf32.f32 "
      "{%0,%1,%2,%3}, {%4,%5,%6,%7}, {%8,%9}, {%0,%1,%2,%3};"
      : "+f"(c[0]), "+f"(c[1]), "+f"(c[2]), "+f"(c[3])
      : "r"(a[0]), "r"(a[1]), "r"(a[2]), "r"(a[3]), "r"(b[0]), "r"(b[1]));
}
__device__ __forceinline__ void mma_f16(float* c, const unsigned* a, const unsigned* b){
    asm volatile(
      "mma.sync.aligned.m16n8k16.row.col.f32.f16.f16.f32 "
      "{%0,%1,%2,%3}, {%4,%5,%6,%7}, {%8,%9}, {%0,%1,%2,%3};"
      : "+f"(c[0]), "+f"(c[1]), "+f"(c[2]), "+f"(c[3])
      : "r"(a[0]), "r"(a[1]), "r"(a[2]), "r"(a[3]), "r"(b[0]), "r"(b[1]));
}

// =============================================================================
// fp32 -> fp16 convert pre-pass (RN; fp16 mantissa == tf32 mantissa)
// =============================================================================
__global__ void to_half(const float4* __restrict__ s, __half* __restrict__ d, int n4)
{
    int i = blockIdx.x * 256 + threadIdx.x;
    if (i >= n4) return;
    float4 v = s[i];
    __half2 h0 = __floats2half2_rn(v.x, v.y);
    __half2 h1 = __floats2half2_rn(v.z, v.w);
    uint2 u;
    u.x = *(unsigned*)&h0; u.y = *(unsigned*)&h1;
    ((uint2*)d)[i] = u;
}

// =============================================================================
// fp16 tensor-core NT GEMM: C[m,n] = sum_k A[m,k]*B[n,k], fp32 accumulate.
// Tile 128x128x64, 128 threads (4 warps, each 64x64), m16n8k16, double-buffered
// cp.async. Smem pitch 72 halves (u32 pitch 36 == 4 mod 32 -> conflict-free frags).
// =============================================================================
#define HP 72                        // smem pitch (halves)
#define HBK 64                       // k per stage (halves)
#define GEMM_SMEM_H (2 * 128 * HP * 2 * 2)   // 73728 B

__global__ void __launch_bounds__(128) gemm_fp16(const __half* __restrict__ A,
                                                 const __half* __restrict__ Bm,
                                                 float* __restrict__ C,
                                                 int M, int N, int K)
{
    extern __shared__ __half shh[];
    __half* As = shh;                   // 2 x [128][HP]
    __half* Bs = shh + 2 * 128 * HP;    // 2 x [128][HP]

    const int tid  = threadIdx.x;
    const int lane = tid & 31, warp = tid >> 5;
    const int g  = lane >> 2, tg = lane & 3;
    const int wm = (warp >> 1) * 64, wn = (warp & 1) * 64;

    const __half* Ag = A  + (size_t)blockIdx.y * 128 * K;
    const __half* Bg = Bm + (size_t)blockIdx.x * 128 * K;

    float c[4][8][4];
    #pragma unroll
    for (int i = 0; i < 4; i++)
        #pragma unroll
        for (int j = 0; j < 8; j++)
            #pragma unroll
            for (int t = 0; t < 4; t++) c[i][j][t] = 0.f;

    const int nkt = K / HBK;

#define HSTAGE(buf, kt) do {                                                 \
    __half* da = As + (buf) * 128 * HP;                                      \
    __half* db = Bs + (buf) * 128 * HP;                                      \
    const __half* sa = Ag + (size_t)(kt) * HBK;                              \
    const __half* sb = Bg + (size_t)(kt) * HBK;                              \
    _Pragma("unroll")                                                        \
    for (int i = 0; i < 8; i++){                                             \
        int idx = i * 128 + tid; int row = idx >> 3; int sg = (idx & 7) * 8; \
        cp16(da + row * HP + sg, sa + (size_t)row * K + sg);                 \
        cp16(db + row * HP + sg, sb + (size_t)row * K + sg);                 \
    }                                                                        \
} while (0)

    HSTAGE(0, 0); cp_commit();

    for (int kt = 0; kt < nkt; kt++) {
        if (kt + 1 < nkt) { HSTAGE((kt + 1) & 1, kt + 1); cp_commit(); cp_wait<1>(); }
        else              { cp_wait<0>(); }
        __syncthreads();

        const unsigned* Ab = (const unsigned*)(As + (kt & 1) * 128 * HP);
        const unsigned* Bb = (const unsigned*)(Bs + (kt & 1) * 128 * HP);

        #pragma unroll
        for (int ks = 0; ks < 4; ks++) {
            const int kc = ks * 8;                     // u32 units (16 halves)
            unsigned a[4][4], bfr[8][2];
            #pragma unroll
            for (int f = 0; f < 4; f++) {
                int ra = wm + f * 16 + g;
                a[f][0] = Ab[ra       * 36 + kc + tg];
                a[f][1] = Ab[(ra + 8) * 36 + kc + tg];
                a[f][2] = Ab[ra       * 36 + kc + tg + 4];
                a[f][3] = Ab[(ra + 8) * 36 + kc + tg + 4];
            }
            #pragma unroll
            for (int f = 0; f < 8; f++) {
                int rb = wn + f * 8 + g;
                bfr[f][0] = Bb[rb * 36 + kc + tg];
                bfr[f][1] = Bb[rb * 36 + kc + tg + 4];
            }
            #pragma unroll
            for (int i = 0; i < 4; i++)
                #pragma unroll
                for (int j = 0; j < 8; j++)
                    mma_f16(c[i][j], a[i], bfr[j]);
        }
        __syncthreads();
    }
#undef HSTAGE

    #pragma unroll
    for (int i = 0; i < 4; i++) {
        int row0 = blockIdx.y * 128 + wm + i * 16 + g;
        #pragma unroll
        for (int j = 0; j < 8; j++) {
            int col = blockIdx.x * 128 + wn + j * 8 + 2 * tg;
            *(float2*)(C + (size_t)row0 * N + col)       = make_float2(c[i][j][0], c[i][j][1]);
            *(float2*)(C + (size_t)(row0 + 8) * N + col) = make_float2(c[i][j][2], c[i][j][3]);
        }
    }
}

// =============================================================================
// Per-head RMSNorm + RoPE core.  One warp per head; lane l owns dims
// {l, l+32, l+64, l+96}.
// =============================================================================
__device__ __forceinline__ void norm_rope_core(const float* __restrict__ inp,
                                               const float* __restrict__ w,
                                               const float* __restrict__ cosT,
                                               const float* __restrict__ sinT,
                                               int pos, int l,
                                               float& o0, float& o1, float& o2, float& o3)
{
    float v0 = inp[l], v1 = inp[l + 32], v2 = inp[l + 64], v3 = inp[l + 96];
    float ss = v0 * v0 + v1 * v1 + v2 * v2 + v3 * v3;
    #pragma unroll
    for (int off = 16; off; off >>= 1) ss += __shfl_xor_sync(0xffffffffu, ss, off);
    float rinv = rsqrtf(ss * (1.f / 128.f) + 1e-6f);
    v0 *= rinv * w[l];      v1 *= rinv * w[l + 32];
    v2 *= rinv * w[l + 64]; v3 *= rinv * w[l + 96];
    const float* c = cosT + (size_t)pos * 128;
    const float* s = sinT + (size_t)pos * 128;
    o0 = v0 * c[l]      - v2 * s[l];
    o1 = v1 * c[l + 32] - v3 * s[l + 32];
    o2 = v2 * c[l + 64] + v0 * s[l + 64];
    o3 = v3 * c[l + 96] + v1 * s[l + 96];
}

// Q: fp32 qkv (row stride NQKV) -> fp16 g_qh (row stride H*HD)
__global__ void q_norm_rope(const float* __restrict__ qkv, __half* __restrict__ qh,
                            const float* __restrict__ w,
                            const float* __restrict__ cosT, const float* __restrict__ sinT,
                            const int* __restrict__ pid)
{
    int bt = blockIdx.x;
    int h  = threadIdx.x >> 5;
    int l  = threadIdx.x & 31;
    const float* base = qkv + (size_t)bt * NQKV + h * HD_;
    float o0, o1, o2, o3;
    norm_rope_core(base, w, cosT, sinT, pid[bt], l, o0, o1, o2, o3);
    __half* ob = qh + (size_t)bt * (H_ * HD_) + h * HD_;
    ob[l]      = __float2half_rn(o0);
    ob[l + 32] = __float2half_rn(o1);
    ob[l + 64] = __float2half_rn(o2);
    ob[l + 96] = __float2half_rn(o3);
}

// K: qkv cols [4096,5120) -> exact fp32 kall (it is an output)
__global__ void k_norm_rope_scatter(const float* __restrict__ qkv,
                                    float* __restrict__ kall,
                                    const float* __restrict__ w,
                                    const float* __restrict__ cosT,
                                    const float* __restrict__ sinT,
                                    const int* __restrict__ pid)
{
    int bt = blockIdx.x;
    int b = bt >> 10, t = bt & 1023;
    int g = threadIdx.x >> 5;
    int l = threadIdx.x & 31;
    const float* src = qkv + (size_t)bt * NQKV + H_ * HD_ + g * HD_;
    float* dst = kall + (((size_t)(b * G_ + g) * SKV) + SPREV + t) * HD_;
    float o0, o1, o2, o3;
    norm_rope_core(src, w, cosT, sinT, pid[bt], l, o0, o1, o2, o3);
    dst[l] = o0; dst[l + 32] = o1; dst[l + 64] = o2; dst[l + 96] = o3;
}

// V in qkv cols [5120, 6144) -> v_all [b,g,SPREV+t,d]
__global__ void v_scatter(const float* __restrict__ qkv, float* __restrict__ vall)
{
    size_t i = (size_t)blockIdx.x * blockDim.x + threadIdx.x;  // 524288 float4s
    int d4 = i & 31;
    int g  = (i >> 5) & 7;
    int bt = (int)(i >> 8);
    int b = bt >> 10, t = bt & 1023;
    size_t src = (size_t)bt * (NQKV / 4) + (H_ * HD_ + G_ * HD_) / 4 + g * 32 + d4;
    size_t dst = (((size_t)(b * G_ + g) * SKV) + SPREV + t) * 32 + d4;
    ((float4*)vall)[dst] = ((const float4*)qkv)[src];
}

__global__ void prev_scatter(const float* __restrict__ pk, const float* __restrict__ pv,
                             float* __restrict__ kall, float* __restrict__ vall)
{
    size_t i = (size_t)blockIdx.x * blockDim.x + threadIdx.x;  // 524288 float4s
    int d4 = i & 31;
    int s  = (i >> 5) & 1023;
    int bg = (int)(i >> 15);
    size_t dst = ((size_t)bg * SKV + s) * 32 + d4;
    ((float4*)kall)[dst] = ((const float4*)pk)[i];
    ((float4*)vall)[dst] = ((const float4*)pv)[i];
}

// =============================================================================
// Tensor-core flash attention: QK^T in fp16 (m16n8k16), PV in tf32 (m16n8k8).
// Block 256 threads (8 warps) = (b, h, 128-query tile); KV tile = 64.
// Smem: Vs fp32 pitch 136, Ps fp32 pitch 68, Qs/Ks half pitch 136
// (u32 pitch 68 == 4 mod 32 -> conflict-free fp16 fragment loads).
// =============================================================================
#define VP 136
#define PP 68
#define ATTN_SMEM 121856   // Vs 34816 + Ps 34816 + Qs 34816 + Ks 17408

__global__ void __launch_bounds__(256) attn_tc(const __half* __restrict__ qh,
                                               const float* __restrict__ kall,
                                               const float* __restrict__ vall,
                                               __half* __restrict__ ctxh)
{
    extern __shared__ char smraw[];
    float*  Vs = (float*)smraw;                       // 64 x VP fp32
    float*  Ps = (float*)(smraw + 34816);             // 128 x PP fp32
    __half* Qs = (__half*)(smraw + 69632);            // 128 x 136 half
    __half* Ks = (__half*)(smraw + 104448);           // 64 x 136 half
    const unsigned* Qs32 = (const unsigned*)Qs;
    const unsigned* Ks32 = (const unsigned*)Ks;

    const int t0 = blockIdx.x * 128;
    const int h  = blockIdx.y;
    const int b  = blockIdx.z;
    const int gk = h >> 2;             // kv group (H/G = 4)
    const int tid = threadIdx.x;
    const int lane = tid & 31, w = tid >> 5;
    const int g = lane >> 2, tg = lane & 3;

    // Q tile (fp16, rows stride H*HD)
    const __half* qbase = qh + (size_t)(b * TQ_ + t0) * (H_ * HD_) + h * HD_;
    #pragma unroll 4
    for (int i = tid; i < 128 * 16; i += 256) {
        int row = i >> 4, c8 = (i & 15) * 8;
        *(uint4*)(Qs + row * 136 + c8) =
            *(const uint4*)(qbase + (size_t)row * (H_ * HD_) + c8);
    }

    const int row0 = 16 * w + g;
    const int qp0 = SPREV + t0 + row0;
    const int qp1 = qp0 + 8;
    const int kv_lim = SPREV + t0 + 128;
    const float scale = 0.08838834764831845f;    // 1/sqrt(128)

    const float* kb = kall + (size_t)(b * G_ + gk) * SKV * HD_;
    const float* vb = vall + (size_t)(b * G_ + gk) * SKV * HD_;

    float oacc[16][4];
    #pragma unroll
    for (int j = 0; j < 16; j++)
        #pragma unroll
        for (int t = 0; t < 4; t++) oacc[j][t] = 0.f;
    float m0 = -1e30f, m1 = -1e30f, l0 = 0.f, l1 = 0.f;

    __syncthreads();

    for (int j0 = 0; j0 < kv_lim; j0 += 64) {
        // K tile: fp32 -> fp16 at store; V tile: fp32, tf32-rounded at store
        #pragma unroll 4
        for (int i = tid; i < 64 * 32; i += 256) {
            int row = i >> 5, c4 = (i & 31) * 4;
            float4 k4 = *(const float4*)(kb + (size_t)(j0 + row) * HD_ + c4);
            __half2 h0 = __floats2half2_rn(k4.x, k4.y);
            __half2 h1 = __floats2half2_rn(k4.z, k4.w);
            uint2 u; u.x = *(unsigned*)&h0; u.y = *(unsigned*)&h1;
            *(uint2*)(Ks + row * 136 + c4) = u;
            float4 v4 = *(const float4*)(vb + (size_t)(j0 + row) * HD_ + c4);
            v4.x = f2tff(v4.x); v4.y = f2tff(v4.y);
            v4.z = f2tff(v4.z); v4.w = f2tff(v4.w);
            *(float4*)(Vs + row * VP + c4) = v4;
        }
        __syncthreads();

        // ---- S = Q K^T  (fp16 m16n8k16, 8 k-steps) ----
        float sacc[8][4];
        #pragma unroll
        for (int j = 0; j < 8; j++)
            #pragma unroll
            for (int t = 0; t < 4; t++) sacc[j][t] = 0.f;

        #pragma unroll
        for (int ks = 0; ks < 8; ks++) {
            const int kc = ks * 8;                    // u32 units
            unsigned a[4];
            a[0] = Qs32[row0       * 68 + kc + tg];
            a[1] = Qs32[(row0 + 8) * 68 + kc + tg];
            a[2] = Qs32[row0       * 68 + kc + tg + 4];
            a[3] = Qs32[(row0 + 8) * 68 + kc + tg + 4];
            #pragma unroll
            for (int j = 0; j < 8; j++) {
                unsigned bb[2];
                bb[0] = Ks32[(8 * j + g) * 68 + kc + tg];
                bb[1] = Ks32[(8 * j + g) * 68 + kc + tg + 4];
                mma_f16(sacc[j], a, bb);
            }
        }

        // ---- softmax on fragments (C layout identical to tf32 path) ----
        const bool nm = (j0 + 63 > SPREV + t0);
        float ml0 = -1e30f, ml1 = -1e30f;
        #pragma unroll
        for (int j = 0; j < 8; j++) {
            if (nm) {
                int c0 = j0 + 8 * j + 2 * tg, c1 = c0 + 1;
                sacc[j][0] = (c0 <= qp0) ? sacc[j][0] * scale : -1e30f;
                sacc[j][1] = (c1 <= qp0) ? sacc[j][1] * scale : -1e30f;
                sacc[j][2] = (c0 <= qp1) ? sacc[j][2] * scale : -1e30f;
                sacc[j][3] = (c1 <= qp1) ? sacc[j][3] * scale : -1e30f;
            } else {
                sacc[j][0] *= scale; sacc[j][1] *= scale;
                sacc[j][2] *= scale; sacc[j][3] *= scale;
            }
            ml0 = fmaxf(ml0, fmaxf(sacc[j][0], sacc[j][1]));
            ml1 = fmaxf(ml1, fmaxf(sacc[j][2], sacc[j][3]));
        }
        ml0 = fmaxf(ml0, __shfl_xor_sync(0xffffffffu, ml0, 1));
        ml0 = fmaxf(ml0, __shfl_xor_sync(0xffffffffu, ml0, 2));
        ml1 = fmaxf(ml1, __shfl_xor_sync(0xffffffffu, ml1, 1));
        ml1 = fmaxf(ml1, __shfl_xor_sync(0xffffffffu, ml1, 2));
        float mn0 = fmaxf(m0, ml0), mn1 = fmaxf(m1, ml1);
        float al0 = __expf(m0 - mn0), al1 = __expf(m1 - mn1);

        float ls0 = 0.f, ls1 = 0.f;
        #pragma unroll
        for (int j = 0; j < 8; j++) {
            float p00 = __expf(sacc[j][0] - mn0);
            float p01 = __expf(sacc[j][1] - mn0);
            float p10 = __expf(sacc[j][2] - mn1);
            float p11 = __expf(sacc[j][3] - mn1);
            ls0 += p00 + p01; ls1 += p10 + p11;
            *(float2*)(Ps + row0       * PP + 8 * j + 2 * tg) =
                make_float2(f2tff(p00), f2tff(p01));
            *(float2*)(Ps + (row0 + 8) * PP + 8 * j + 2 * tg) =
                make_float2(f2tff(p10), f2tff(p11));
        }
        ls0 += __shfl_xor_sync(0xffffffffu, ls0, 1);
        ls0 += __shfl_xor_sync(0xffffffffu, ls0, 2);
        ls1 += __shfl_xor_sync(0xffffffffu, ls1, 1);
        ls1 += __shfl_xor_sync(0xffffffffu, ls1, 2);
        l0 = l0 * al0 + ls0;  m0 = mn0;
        l1 = l1 * al1 + ls1;  m1 = mn1;

        #pragma unroll
        for (int j = 0; j < 16; j++) {
            oacc[j][0] *= al0; oacc[j][1] *= al0;
            oacc[j][2] *= al1; oacc[j][3] *= al1;
        }
        __syncwarp();

        // ---- O += P V  (tf32 m16n8k8, raw-bit fragments) ----
        #pragma unroll
        for (int ks = 0; ks < 8; ks++) {
            const int kc = ks * 8;
            unsigned a[4];
            a[0] = __float_as_uint(Ps[row0       * PP + kc + tg]);
            a[1] = __float_as_uint(Ps[(row0 + 8) * PP + kc + tg]);
            a[2] = __float_as_uint(Ps[row0       * PP + kc + tg + 4]);
            a[3] = __float_as_uint(Ps[(row0 + 8) * PP + kc + tg + 4]);
            #pragma unroll
            for (int j = 0; j < 16; j++) {
                unsigned bfr[2];
                bfr[0] = __float_as_uint(Vs[(kc + tg)     * VP + 8 * j + g]);
                bfr[1] = __float_as_uint(Vs[(kc + tg + 4) * VP + 8 * j + g]);
                mma_tf32(oacc[j], a, bfr);
            }
        }
        __syncthreads();
    }

    // epilogue: fp16 ctx (feeds fp16 out-projection A operand)
    float i0 = 1.f / l0, i1 = 1.f / l1;
    __half* c0p = ctxh + ((size_t)(b * TQ_ + t0 + row0)     * H_ + h) * HD_;
    __half* c1p = ctxh + ((size_t)(b * TQ_ + t0 + row0 + 8) * H_ + h) * HD_;
    #pragma unroll
    for (int j = 0; j < 16; j++) {
        int col = 8 * j + 2 * tg;
        *(__half2*)(c0p + col) = __floats2half2_rn(oacc[j][0] * i0, oacc[j][1] * i0);
        *(__half2*)(c1p + col) = __floats2half2_rn(oacc[j][2] * i1, oacc[j][3] * i1);
    }
}

// =============================================================================
// host launcher
// =============================================================================
template<typename T>
static T* sym_addr_t(const void* symbol)
{
    void* p = nullptr;
    cudaGetSymbolAddress(&p, symbol);
    return (T*)p;
}

extern "C" void kernel_launch(void* const* d_in, const int* in_sizes, int n_in,
                              void* d_out, int out_size)
{
    const float* x    = (const float*)d_in[0];
    const float* Wq   = (const float*)d_in[1];
    const float* Wk   = (const float*)d_in[2];
    const float* Wv   = (const float*)d_in[3];
    const float* Wo   = (const float*)d_in[4];
    const float* qw   = (const float*)d_in[5];
    const float* kw   = (const float*)d_in[6];
    const float* cosT = (const float*)d_in[7];
    const float* sinT = (const float*)d_in[8];
    const float* pk   = (const float*)d_in[9];
    const float* pv   = (const float*)d_in[10];
    const int*   pid  = (const int*)d_in[11];
    // d_in[12] = mask, computed analytically

    float* out  = (float*)d_out;                                    // B*T*DIN
    float* kall = out  + (size_t)B_ * TQ_ * DIN_;                   // B*G*SKV*HD
    float* vall = kall + (size_t)B_ * G_ * SKV * HD_;

    float*  qkv   = sym_addr_t<float>(g_qkv);
    __half* xh    = sym_addr_t<__half>(g_xh);
    __half* wqkvh = sym_addr_t<__half>(g_wqkvh);
    __half* woh   = sym_addr_t<__half>(g_woh);
    __half* qh    = sym_addr_t<__half>(g_qh);
    __half* ctxh  = sym_addr_t<__half>(g_ctxh);

    cudaFuncSetAttribute(gemm_fp16, cudaFuncAttributeMaxDynamicSharedMemorySize, GEMM_SMEM_H);
    cudaFuncSetAttribute(attn_tc,   cudaFuncAttributeMaxDynamicSharedMemorySize, ATTN_SMEM);

    // 1-5) fp32 -> fp16 convert pre-pass
    to_half<<< 8192, 256>>>((const float4*)x,  xh,                    2097152);
    to_half<<<16384, 256>>>((const float4*)Wq, wqkvh,                 4194304);
    to_half<<< 4096, 256>>>((const float4*)Wk, wqkvh + 16777216,      1048576);
    to_half<<< 4096, 256>>>((const float4*)Wv, wqkvh + 20971520,      1048576);
    to_half<<<16384, 256>>>((const float4*)Wo, woh,                   4194304);

    // 6) fused QKV projection: [2048 x 6144] = xh @ [Wq;Wk;Wv]^T  (fp32 out)
    gemm_fp16<<<dim3(NQKV / 128, BT_ / 128), 128, GEMM_SMEM_H>>>(xh, wqkvh, qkv, BT_, NQKV, DIN_);

    // 7) prev kv cache copy
    prev_scatter<<<2048, 256>>>(pk, pv, kall, vall);

    // 8-10) norm + rope + kv assembly
    q_norm_rope<<<BT_, H_ * 32>>>(qkv, qh, qw, cosT, sinT, pid);
    k_norm_rope_scatter<<<BT_, G_ * 32>>>(qkv, kall, kw, cosT, sinT, pid);
    v_scatter<<<2048, 256>>>(qkv, vall);

    // 11) attention
    attn_tc<<<dim3(TQ_ / 128, H_, B_), 256, ATTN_SMEM>>>(qh, kall, vall, ctxh);

    // 12) output projection
    gemm_fp16<<<dim3(DIN_ / 128, BT_ / 128), 128, GEMM_SMEM_H>>>(ctxh, woh, out, BT_, DIN_, DIN_);

    (void)in_sizes; (void)n_in; (void)out_size;
}

// round 12
// speedup vs baseline: 19.4808x; 1.2244x over previous
#include <cuda_runtime.h>
#include <cuda_bf16.h>
#include <cuda_fp16.h>
#include <cstdint>

// Problem constants
#define B_    2
#define TQ_   1024
#define DIN_  4096
#define H_    32
#define G_    8
#define HD_   128
#define SPREV 1024
#define SKV   2048          // SPREV + TQ
#define BT_   (B_*TQ_)      // 2048
#define NQKV  6144          // H*HD + 2*G*HD

// ---------------- scratch (no allocation allowed -> __device__ globals) ---------
__device__ float  g_qkv [(size_t)BT_ * NQKV];        // fused q|k|v projections (fp32)
__device__ __half g_xh  [(size_t)BT_ * DIN_];        // fp16 x
__device__ __half g_wqkvh[(size_t)NQKV * DIN_];      // fp16 [Wq;Wk;Wv]
__device__ __half g_woh [(size_t)DIN_ * H_ * HD_];   // fp16 Wo
__device__ __half g_qh  [(size_t)BT_ * H_ * HD_];    // fp16 Q (post norm+rope)
__device__ __half g_ctxh[(size_t)BT_ * H_ * HD_];    // fp16 attention output

// =============================================================================
// helpers
// =============================================================================
__device__ __forceinline__ void cp16(void* s, const void* g){
    unsigned sa = (unsigned)__cvta_generic_to_shared(s);
    asm volatile("cp.async.cg.shared.global [%0], [%1], 16;\n" :: "r"(sa), "l"(g));
}
__device__ __forceinline__ void cp_commit(){ asm volatile("cp.async.commit_group;\n" ::); }
template<int NN> __device__ __forceinline__ void cp_wait(){
    asm volatile("cp.async.wait_group %0;\n" :: "n"(NN));
}
__device__ __forceinline__ void mma_f16(float* c, const unsigned* a, const unsigned* b){
    asm volatile(
      "mma.sync.aligned.m16n8k16.row.col.f32.f16.f16.f32 "
      "{%0,%1,%2,%3}, {%4,%5,%6,%7}, {%8,%9}, {%0,%1,%2,%3};"
      : "+f"(c[0]), "+f"(c[1]), "+f"(c[2]), "+f"(c[3])
      : "r"(a[0]), "r"(a[1]), "r"(a[2]), "r"(a[3]), "r"(b[0]), "r"(b[1]));
}
__device__ __forceinline__ void ldsm_x4_trans(unsigned& r0, unsigned& r1,
                                              unsigned& r2, unsigned& r3,
                                              const void* p){
    unsigned sa = (unsigned)__cvta_generic_to_shared(p);
    asm volatile("ldmatrix.sync.aligned.m8n8.x4.trans.shared.b16 {%0,%1,%2,%3}, [%4];"
                 : "=r"(r0), "=r"(r1), "=r"(r2), "=r"(r3) : "r"(sa));
}

// =============================================================================
// fp32 -> fp16 convert pre-pass
// =============================================================================
__global__ void to_half(const float4* __restrict__ s, __half* __restrict__ d, int n4)
{
    int i = blockIdx.x * 256 + threadIdx.x;
    if (i >= n4) return;
    float4 v = s[i];
    __half2 h0 = __floats2half2_rn(v.x, v.y);
    __half2 h1 = __floats2half2_rn(v.z, v.w);
    uint2 u;
    u.x = *(unsigned*)&h0; u.y = *(unsigned*)&h1;
    ((uint2*)d)[i] = u;
}

// =============================================================================
// fp16 tensor-core NT GEMM: C[m,n] = sum_k A[m,k]*B[n,k], fp32 accumulate.
// Tile 128x128x64, 128 threads (4 warps, each 64x64), m16n8k16, double-buffered
// cp.async. Smem pitch 72 halves (u32 pitch 36 == 4 mod 32 -> conflict-free frags).
// =============================================================================
#define HP 72                        // smem pitch (halves)
#define HBK 64                       // k per stage (halves)
#define GEMM_SMEM_H (2 * 128 * HP * 2 * 2)   // 73728 B

__global__ void __launch_bounds__(128) gemm_fp16(const __half* __restrict__ A,
                                                 const __half* __restrict__ Bm,
                                                 float* __restrict__ C,
                                                 int M, int N, int K)
{
    extern __shared__ __half shh[];
    __half* As = shh;                   // 2 x [128][HP]
    __half* Bs = shh + 2 * 128 * HP;    // 2 x [128][HP]

    const int tid  = threadIdx.x;
    const int lane = tid & 31, warp = tid >> 5;
    const int g  = lane >> 2, tg = lane & 3;
    const int wm = (warp >> 1) * 64, wn = (warp & 1) * 64;

    const __half* Ag = A  + (size_t)blockIdx.y * 128 * K;
    const __half* Bg = Bm + (size_t)blockIdx.x * 128 * K;

    float c[4][8][4];
    #pragma unroll
    for (int i = 0; i < 4; i++)
        #pragma unroll
        for (int j = 0; j < 8; j++)
            #pragma unroll
            for (int t = 0; t < 4; t++) c[i][j][t] = 0.f;

    const int nkt = K / HBK;

#define HSTAGE(buf, kt) do {                                                 \
    __half* da = As + (buf) * 128 * HP;                                      \
    __half* db = Bs + (buf) * 128 * HP;                                      \
    const __half* sa = Ag + (size_t)(kt) * HBK;                              \
    const __half* sb = Bg + (size_t)(kt) * HBK;                              \
    _Pragma("unroll")                                                        \
    for (int i = 0; i < 8; i++){                                             \
        int idx = i * 128 + tid; int row = idx >> 3; int sg = (idx & 7) * 8; \
        cp16(da + row * HP + sg, sa + (size_t)row * K + sg);                 \
        cp16(db + row * HP + sg, sb + (size_t)row * K + sg);                 \
    }                                                                        \
} while (0)

    HSTAGE(0, 0); cp_commit();

    for (int kt = 0; kt < nkt; kt++) {
        if (kt + 1 < nkt) { HSTAGE((kt + 1) & 1, kt + 1); cp_commit(); cp_wait<1>(); }
        else              { cp_wait<0>(); }
        __syncthreads();

        const unsigned* Ab = (const unsigned*)(As + (kt & 1) * 128 * HP);
        const unsigned* Bb = (const unsigned*)(Bs + (kt & 1) * 128 * HP);

        #pragma unroll
        for (int ks = 0; ks < 4; ks++) {
            const int kc = ks * 8;                     // u32 units (16 halves)
            unsigned a[4][4], bfr[8][2];
            #pragma unroll
            for (int f = 0; f < 4; f++) {
                int ra = wm + f * 16 + g;
                a[f][0] = Ab[ra       * 36 + kc + tg];
                a[f][1] = Ab[(ra + 8) * 36 + kc + tg];
                a[f][2] = Ab[ra       * 36 + kc + tg + 4];
                a[f][3] = Ab[(ra + 8) * 36 + kc + tg + 4];
            }
            #pragma unroll
            for (int f = 0; f < 8; f++) {
                int rb = wn + f * 8 + g;
                bfr[f][0] = Bb[rb * 36 + kc + tg];
                bfr[f][1] = Bb[rb * 36 + kc + tg + 4];
            }
            #pragma unroll
            for (int i = 0; i < 4; i++)
                #pragma unroll
                for (int j = 0; j < 8; j++)
                    mma_f16(c[i][j], a[i], bfr[j]);
        }
        __syncthreads();
    }
#undef HSTAGE

    #pragma unroll
    for (int i = 0; i < 4; i++) {
        int row0 = blockIdx.y * 128 + wm + i * 16 + g;
        #pragma unroll
        for (int j = 0; j < 8; j++) {
            int col = blockIdx.x * 128 + wn + j * 8 + 2 * tg;
            *(float2*)(C + (size_t)row0 * N + col)       = make_float2(c[i][j][0], c[i][j][1]);
            *(float2*)(C + (size_t)(row0 + 8) * N + col) = make_float2(c[i][j][2], c[i][j][3]);
        }
    }
}

// =============================================================================
// Per-head RMSNorm + RoPE core.  One warp per head; lane l owns dims
// {l, l+32, l+64, l+96}.
// =============================================================================
__device__ __forceinline__ void norm_rope_core(const float* __restrict__ inp,
                                               const float* __restrict__ w,
                                               const float* __restrict__ cosT,
                                               const float* __restrict__ sinT,
                                               int pos, int l,
                                               float& o0, float& o1, float& o2, float& o3)
{
    float v0 = inp[l], v1 = inp[l + 32], v2 = inp[l + 64], v3 = inp[l + 96];
    float ss = v0 * v0 + v1 * v1 + v2 * v2 + v3 * v3;
    #pragma unroll
    for (int off = 16; off; off >>= 1) ss += __shfl_xor_sync(0xffffffffu, ss, off);
    float rinv = rsqrtf(ss * (1.f / 128.f) + 1e-6f);
    v0 *= rinv * w[l];      v1 *= rinv * w[l + 32];
    v2 *= rinv * w[l + 64]; v3 *= rinv * w[l + 96];
    const float* c = cosT + (size_t)pos * 128;
    const float* s = sinT + (size_t)pos * 128;
    o0 = v0 * c[l]      - v2 * s[l];
    o1 = v1 * c[l + 32] - v3 * s[l + 32];
    o2 = v2 * c[l + 64] + v0 * s[l + 64];
    o3 = v3 * c[l + 96] + v1 * s[l + 96];
}

// Q: fp32 qkv (row stride NQKV) -> fp16 g_qh (row stride H*HD)
__global__ void q_norm_rope(const float* __restrict__ qkv, __half* __restrict__ qh,
                            const float* __restrict__ w,
                            const float* __restrict__ cosT, const float* __restrict__ sinT,
                            const int* __restrict__ pid)
{
    int bt = blockIdx.x;
    int h  = threadIdx.x >> 5;
    int l  = threadIdx.x & 31;
    const float* base = qkv + (size_t)bt * NQKV + h * HD_;
    float o0, o1, o2, o3;
    norm_rope_core(base, w, cosT, sinT, pid[bt], l, o0, o1, o2, o3);
    __half* ob = qh + (size_t)bt * (H_ * HD_) + h * HD_;
    ob[l]      = __float2half_rn(o0);
    ob[l + 32] = __float2half_rn(o1);
    ob[l + 64] = __float2half_rn(o2);
    ob[l + 96] = __float2half_rn(o3);
}

// K: qkv cols [4096,5120) -> exact fp32 kall (it is an output)
__global__ void k_norm_rope_scatter(const float* __restrict__ qkv,
                                    float* __restrict__ kall,
                                    const float* __restrict__ w,
                                    const float* __restrict__ cosT,
                                    const float* __restrict__ sinT,
                                    const int* __restrict__ pid)
{
    int bt = blockIdx.x;
    int b = bt >> 10, t = bt & 1023;
    int g = threadIdx.x >> 5;
    int l = threadIdx.x & 31;
    const float* src = qkv + (size_t)bt * NQKV + H_ * HD_ + g * HD_;
    float* dst = kall + (((size_t)(b * G_ + g) * SKV) + SPREV + t) * HD_;
    float o0, o1, o2, o3;
    norm_rope_core(src, w, cosT, sinT, pid[bt], l, o0, o1, o2, o3);
    dst[l] = o0; dst[l + 32] = o1; dst[l + 64] = o2; dst[l + 96] = o3;
}

// V in qkv cols [5120, 6144) -> v_all [b,g,SPREV+t,d]
__global__ void v_scatter(const float* __restrict__ qkv, float* __restrict__ vall)
{
    size_t i = (size_t)blockIdx.x * blockDim.x + threadIdx.x;  // 524288 float4s
    int d4 = i & 31;
    int g  = (i >> 5) & 7;
    int bt = (int)(i >> 8);
    int b = bt >> 10, t = bt & 1023;
    size_t src = (size_t)bt * (NQKV / 4) + (H_ * HD_ + G_ * HD_) / 4 + g * 32 + d4;
    size_t dst = (((size_t)(b * G_ + g) * SKV) + SPREV + t) * 32 + d4;
    ((float4*)vall)[dst] = ((const float4*)qkv)[src];
}

__global__ void prev_scatter(const float* __restrict__ pk, const float* __restrict__ pv,
                             float* __restrict__ kall, float* __restrict__ vall)
{
    size_t i = (size_t)blockIdx.x * blockDim.x + threadIdx.x;  // 524288 float4s
    int d4 = i & 31;
    int s  = (i >> 5) & 1023;
    int bg = (int)(i >> 15);
    size_t dst = ((size_t)bg * SKV + s) * 32 + d4;
    ((float4*)kall)[dst] = ((const float4*)pk)[i];
    ((float4*)vall)[dst] = ((const float4*)pv)[i];
}

// =============================================================================
// Full-fp16 tensor-core flash attention (m16n8k16 everywhere, fp32 accum).
// Block 256 threads (8 warps) = (b, h, 128-query tile); KV tile = 64.
// Smem (all half): Qs 128x136, Ks 64x136, Vs 64x136 (row-major; PV B-frags via
// ldmatrix.x4.trans), Ps 128x72. 88064 B -> 2 CTAs/SM.
// =============================================================================
#define ATTN_SMEM 88064

__global__ void __launch_bounds__(256, 2) attn_tc(const __half* __restrict__ qh,
                                                  const float* __restrict__ kall,
                                                  const float* __restrict__ vall,
                                                  __half* __restrict__ ctxh)
{
    extern __shared__ char smraw[];
    __half* Qs  = (__half*)smraw;                     // 128 x 136
    __half* Ks  = (__half*)(smraw + 34816);           // 64 x 136
    __half* Vs  = (__half*)(smraw + 52224);           // 64 x 136 (row-major [k][n])
    __half* PsH = (__half*)(smraw + 69632);           // 128 x 72
    const unsigned* Qs32 = (const unsigned*)Qs;
    const unsigned* Ks32 = (const unsigned*)Ks;
    const unsigned* Ps32 = (const unsigned*)PsH;

    const int t0 = blockIdx.x * 128;
    const int h  = blockIdx.y;
    const int b  = blockIdx.z;
    const int gk = h >> 2;             // kv group (H/G = 4)
    const int tid = threadIdx.x;
    const int lane = tid & 31, w = tid >> 5;
    const int g = lane >> 2, tg = lane & 3;

    // Q tile (fp16, rows stride H*HD)
    const __half* qbase = qh + (size_t)(b * TQ_ + t0) * (H_ * HD_) + h * HD_;
    #pragma unroll 4
    for (int i = tid; i < 128 * 16; i += 256) {
        int row = i >> 4, c8 = (i & 15) * 8;
        *(uint4*)(Qs + row * 136 + c8) =
            *(const uint4*)(qbase + (size_t)row * (H_ * HD_) + c8);
    }

    const int row0 = 16 * w + g;
    const int qp0 = SPREV + t0 + row0;
    const int qp1 = qp0 + 8;
    const int kv_lim = SPREV + t0 + 128;
    const float scale = 0.08838834764831845f;    // 1/sqrt(128)

    // ldmatrix.x4.trans lane address for V: rows k0+(lane&15), col n0+((lane>>4)<<3)
    const int vrow_l = lane & 15;
    const int vcol_l = (lane >> 4) << 3;

    const float* kb = kall + (size_t)(b * G_ + gk) * SKV * HD_;
    const float* vb = vall + (size_t)(b * G_ + gk) * SKV * HD_;

    float oacc[16][4];
    #pragma unroll
    for (int j = 0; j < 16; j++)
        #pragma unroll
        for (int t = 0; t < 4; t++) oacc[j][t] = 0.f;
    float m0 = -1e30f, m1 = -1e30f, l0 = 0.f, l1 = 0.f;

    __syncthreads();

    for (int j0 = 0; j0 < kv_lim; j0 += 64) {
        // K,V tiles: fp32 gmem -> fp16 smem (row-major both)
        #pragma unroll 4
        for (int i = tid; i < 64 * 32; i += 256) {
            int row = i >> 5, c4 = (i & 31) * 4;
            float4 k4 = *(const float4*)(kb + (size_t)(j0 + row) * HD_ + c4);
            __half2 h0 = __floats2half2_rn(k4.x, k4.y);
            __half2 h1 = __floats2half2_rn(k4.z, k4.w);
            uint2 u; u.x = *(unsigned*)&h0; u.y = *(unsigned*)&h1;
            *(uint2*)(Ks + row * 136 + c4) = u;
            float4 v4 = *(const float4*)(vb + (size_t)(j0 + row) * HD_ + c4);
            __half2 h2 = __floats2half2_rn(v4.x, v4.y);
            __half2 h3 = __floats2half2_rn(v4.z, v4.w);
            uint2 uv; uv.x = *(unsigned*)&h2; uv.y = *(unsigned*)&h3;
            *(uint2*)(Vs + row * 136 + c4) = uv;
        }
        __syncthreads();

        // ---- S = Q K^T  (fp16 m16n8k16, 8 k-steps) ----
        float sacc[8][4];
        #pragma unroll
        for (int j = 0; j < 8; j++)
            #pragma unroll
            for (int t = 0; t < 4; t++) sacc[j][t] = 0.f;

        #pragma unroll
        for (int ks = 0; ks < 8; ks++) {
            const int kc = ks * 8;                    // u32 units
            unsigned a[4];
            a[0] = Qs32[row0       * 68 + kc + tg];
            a[1] = Qs32[(row0 + 8) * 68 + kc + tg];
            a[2] = Qs32[row0       * 68 + kc + tg + 4];
            a[3] = Qs32[(row0 + 8) * 68 + kc + tg + 4];
            #pragma unroll
            for (int j = 0; j < 8; j++) {
                unsigned bb[2];
                bb[0] = Ks32[(8 * j + g) * 68 + kc + tg];
                bb[1] = Ks32[(8 * j + g) * 68 + kc + tg + 4];
                mma_f16(sacc[j], a, bb);
            }
        }

        // ---- softmax on fragments ----
        const bool nm = (j0 + 63 > SPREV + t0);
        float ml0 = -1e30f, ml1 = -1e30f;
        #pragma unroll
        for (int j = 0; j < 8; j++) {
            if (nm) {
                int c0 = j0 + 8 * j + 2 * tg, c1 = c0 + 1;
                sacc[j][0] = (c0 <= qp0) ? sacc[j][0] * scale : -1e30f;
                sacc[j][1] = (c1 <= qp0) ? sacc[j][1] * scale : -1e30f;
                sacc[j][2] = (c0 <= qp1) ? sacc[j][2] * scale : -1e30f;
                sacc[j][3] = (c1 <= qp1) ? sacc[j][3] * scale : -1e30f;
            } else {
                sacc[j][0] *= scale; sacc[j][1] *= scale;
                sacc[j][2] *= scale; sacc[j][3] *= scale;
            }
            ml0 = fmaxf(ml0, fmaxf(sacc[j][0], sacc[j][1]));
            ml1 = fmaxf(ml1, fmaxf(sacc[j][2], sacc[j][3]));
        }
        ml0 = fmaxf(ml0, __shfl_xor_sync(0xffffffffu, ml0, 1));
        ml0 = fmaxf(ml0, __shfl_xor_sync(0xffffffffu, ml0, 2));
        ml1 = fmaxf(ml1, __shfl_xor_sync(0xffffffffu, ml1, 1));
        ml1 = fmaxf(ml1, __shfl_xor_sync(0xffffffffu, ml1, 2));
        float mn0 = fmaxf(m0, ml0), mn1 = fmaxf(m1, ml1);
        float al0 = __expf(m0 - mn0), al1 = __expf(m1 - mn1);

        float ls0 = 0.f, ls1 = 0.f;
        #pragma unroll
        for (int j = 0; j < 8; j++) {
            float p00 = __expf(sacc[j][0] - mn0);
            float p01 = __expf(sacc[j][1] - mn0);
            float p10 = __expf(sacc[j][2] - mn1);
            float p11 = __expf(sacc[j][3] - mn1);
            ls0 += p00 + p01; ls1 += p10 + p11;
            *(__half2*)(PsH + row0       * 72 + 8 * j + 2 * tg) = __floats2half2_rn(p00, p01);
            *(__half2*)(PsH + (row0 + 8) * 72 + 8 * j + 2 * tg) = __floats2half2_rn(p10, p11);
        }
        ls0 += __shfl_xor_sync(0xffffffffu, ls0, 1);
        ls0 += __shfl_xor_sync(0xffffffffu, ls0, 2);
        ls1 += __shfl_xor_sync(0xffffffffu, ls1, 1);
        ls1 += __shfl_xor_sync(0xffffffffu, ls1, 2);
        l0 = l0 * al0 + ls0;  m0 = mn0;
        l1 = l1 * al1 + ls1;  m1 = mn1;

        #pragma unroll
        for (int j = 0; j < 16; j++) {
            oacc[j][0] *= al0; oacc[j][1] *= al0;
            oacc[j][2] *= al1; oacc[j][3] *= al1;
        }
        __syncwarp();   // P rows of this warp: cross-lane STS->LDS visibility

        // ---- O += P V  (fp16 m16n8k16; V B-frags via ldmatrix.x4.trans) ----
        #pragma unroll
        for (int ks = 0; ks < 4; ks++) {
            unsigned a[4];
            a[0] = Ps32[row0       * 36 + 8 * ks + tg];
            a[1] = Ps32[(row0 + 8) * 36 + 8 * ks + tg];
            a[2] = Ps32[row0       * 36 + 8 * ks + tg + 4];
            a[3] = Ps32[(row0 + 8) * 36 + 8 * ks + tg + 4];
            #pragma unroll
            for (int j2 = 0; j2 < 8; j2++) {
                unsigned r0, r1, r2, r3;
                const __half* vp = Vs + (ks * 16 + vrow_l) * 136 + j2 * 16 + vcol_l;
                ldsm_x4_trans(r0, r1, r2, r3, vp);
                unsigned b0[2] = { r0, r1 };
                unsigned b1[2] = { r2, r3 };
                mma_f16(oacc[2 * j2],     a, b0);
                mma_f16(oacc[2 * j2 + 1], a, b1);
            }
        }
        __syncthreads();
    }

    // epilogue: fp16 ctx (feeds fp16 out-projection A operand)
    float i0 = 1.f / l0, i1 = 1.f / l1;
    __half* c0p = ctxh + ((size_t)(b * TQ_ + t0 + row0)     * H_ + h) * HD_;
    __half* c1p = ctxh + ((size_t)(b * TQ_ + t0 + row0 + 8) * H_ + h) * HD_;
    #pragma unroll
    for (int j = 0; j < 16; j++) {
        int col = 8 * j + 2 * tg;
        *(__half2*)(c0p + col) = __floats2half2_rn(oacc[j][0] * i0, oacc[j][1] * i0);
        *(__half2*)(c1p + col) = __floats2half2_rn(oacc[j][2] * i1, oacc[j][3] * i1);
    }
}

// =============================================================================
// host launcher
// =============================================================================
template<typename T>
static T* sym_addr_t(const void* symbol)
{
    void* p = nullptr;
    cudaGetSymbolAddress(&p, symbol);
    return (T*)p;
}

extern "C" void kernel_launch(void* const* d_in, const int* in_sizes, int n_in,
                              void* d_out, int out_size)
{
    const float* x    = (const float*)d_in[0];
    const float* Wq   = (const float*)d_in[1];
    const float* Wk   = (const float*)d_in[2];
    const float* Wv   = (const float*)d_in[3];
    const float* Wo   = (const float*)d_in[4];
    const float* qw   = (const float*)d_in[5];
    const float* kw   = (const float*)d_in[6];
    const float* cosT = (const float*)d_in[7];
    const float* sinT = (const float*)d_in[8];
    const float* pk   = (const float*)d_in[9];
    const float* pv   = (const float*)d_in[10];
    const int*   pid  = (const int*)d_in[11];
    // d_in[12] = mask, computed analytically

    float* out  = (float*)d_out;                                    // B*T*DIN
    float* kall = out  + (size_t)B_ * TQ_ * DIN_;                   // B*G*SKV*HD
    float* vall = kall + (size_t)B_ * G_ * SKV * HD_;

    float*  qkv   = sym_addr_t<float>(g_qkv);
    __half* xh    = sym_addr_t<__half>(g_xh);
    __half* wqkvh = sym_addr_t<__half>(g_wqkvh);
    __half* woh   = sym_addr_t<__half>(g_woh);
    __half* qh    = sym_addr_t<__half>(g_qh);
    __half* ctxh  = sym_addr_t<__half>(g_ctxh);

    cudaFuncSetAttribute(gemm_fp16, cudaFuncAttributeMaxDynamicSharedMemorySize, GEMM_SMEM_H);
    cudaFuncSetAttribute(attn_tc,   cudaFuncAttributeMaxDynamicSharedMemorySize, ATTN_SMEM);

    // 1-5) fp32 -> fp16 convert pre-pass
    to_half<<< 8192, 256>>>((const float4*)x,  xh,                    2097152);
    to_half<<<16384, 256>>>((const float4*)Wq, wqkvh,                 4194304);
    to_half<<< 4096, 256>>>((const float4*)Wk, wqkvh + 16777216,      1048576);
    to_half<<< 4096, 256>>>((const float4*)Wv, wqkvh + 20971520,      1048576);
    to_half<<<16384, 256>>>((const float4*)Wo, woh,                   4194304);

    // 6) fused QKV projection: [2048 x 6144] = xh @ [Wq;Wk;Wv]^T  (fp32 out)
    gemm_fp16<<<dim3(NQKV / 128, BT_ / 128), 128, GEMM_SMEM_H>>>(xh, wqkvh, qkv, BT_, NQKV, DIN_);

    // 7) prev kv cache copy
    prev_scatter<<<2048, 256>>>(pk, pv, kall, vall);

    // 8-10) norm + rope + kv assembly
    q_norm_rope<<<BT_, H_ * 32>>>(qkv, qh, qw, cosT, sinT, pid);
    k_norm_rope_scatter<<<BT_, G_ * 32>>>(qkv, kall, kw, cosT, sinT, pid);
    v_scatter<<<2048, 256>>>(qkv, vall);

    // 11) attention (full fp16)
    attn_tc<<<dim3(TQ_ / 128, H_, B_), 256, ATTN_SMEM>>>(qh, kall, vall, ctxh);

    // 12) output projection
    gemm_fp16<<<dim3(DIN_ / 128, BT_ / 128), 128, GEMM_SMEM_H>>>(ctxh, woh, out, BT_, DIN_, DIN_);

    (void)in_sizes; (void)n_in; (void)out_size;
}

// round 13
// speedup vs baseline: 21.4600x; 1.1016x over previous
#include <cuda_runtime.h>
#include <cuda_bf16.h>
#include <cuda_fp16.h>
#include <cstdint>

// Problem constants
#define B_    2
#define TQ_   1024
#define DIN_  4096
#define H_    32
#define G_    8
#define HD_   128
#define SPREV 1024
#define SKV   2048          // SPREV + TQ
#define BT_   (B_*TQ_)      // 2048
#define NQKV  6144          // H*HD + 2*G*HD

// ---------------- scratch (no allocation allowed -> __device__ globals) ---------
__device__ float  g_qkv [(size_t)BT_ * NQKV];        // fused q|k|v projections (fp32)
__device__ __half g_xh  [(size_t)BT_ * DIN_];        // fp16 x
__device__ __half g_wqkvh[(size_t)NQKV * DIN_];      // fp16 [Wq;Wk;Wv]
__device__ __half g_woh [(size_t)DIN_ * H_ * HD_];   // fp16 Wo
__device__ __half g_qh  [(size_t)BT_ * H_ * HD_];    // fp16 Q (post norm+rope)
__device__ __half g_ctxh[(size_t)BT_ * H_ * HD_];    // fp16 attention output

// =============================================================================
// helpers
// =============================================================================
__device__ __forceinline__ void cp16(void* s, const void* g){
    unsigned sa = (unsigned)__cvta_generic_to_shared(s);
    asm volatile("cp.async.cg.shared.global [%0], [%1], 16;\n" :: "r"(sa), "l"(g));
}
__device__ __forceinline__ void cp_commit(){ asm volatile("cp.async.commit_group;\n" ::); }
template<int NN> __device__ __forceinline__ void cp_wait(){
    asm volatile("cp.async.wait_group %0;\n" :: "n"(NN));
}
__device__ __forceinline__ void mma_f16(float* c, const unsigned* a, const unsigned* b){
    asm volatile(
      "mma.sync.aligned.m16n8k16.row.col.f32.f16.f16.f32 "
      "{%0,%1,%2,%3}, {%4,%5,%6,%7}, {%8,%9}, {%0,%1,%2,%3};"
      : "+f"(c[0]), "+f"(c[1]), "+f"(c[2]), "+f"(c[3])
      : "r"(a[0]), "r"(a[1]), "r"(a[2]), "r"(a[3]), "r"(b[0]), "r"(b[1]));
}
__device__ __forceinline__ void ldsm_x4(unsigned& r0, unsigned& r1,
                                        unsigned& r2, unsigned& r3,
                                        const void* p){
    unsigned sa = (unsigned)__cvta_generic_to_shared(p);
    asm volatile("ldmatrix.sync.aligned.m8n8.x4.shared.b16 {%0,%1,%2,%3}, [%4];"
                 : "=r"(r0), "=r"(r1), "=r"(r2), "=r"(r3) : "r"(sa));
}
__device__ __forceinline__ void ldsm_x4_trans(unsigned& r0, unsigned& r1,
                                              unsigned& r2, unsigned& r3,
                                              const void* p){
    unsigned sa = (unsigned)__cvta_generic_to_shared(p);
    asm volatile("ldmatrix.sync.aligned.m8n8.x4.trans.shared.b16 {%0,%1,%2,%3}, [%4];"
                 : "=r"(r0), "=r"(r1), "=r"(r2), "=r"(r3) : "r"(sa));
}

// =============================================================================
// fp32 -> fp16 convert pre-pass
// =============================================================================
__global__ void to_half(const float4* __restrict__ s, __half* __restrict__ d, int n4)
{
    int i = blockIdx.x * 256 + threadIdx.x;
    if (i >= n4) return;
    float4 v = s[i];
    __half2 h0 = __floats2half2_rn(v.x, v.y);
    __half2 h1 = __floats2half2_rn(v.z, v.w);
    uint2 u;
    u.x = *(unsigned*)&h0; u.y = *(unsigned*)&h1;
    ((uint2*)d)[i] = u;
}

// =============================================================================
// fp16 tensor-core NT GEMM: C[m,n] = sum_k A[m,k]*B[n,k], fp32 accumulate.
// Tile 128x128x64, 128 threads (4 warps, each 64x64), m16n8k16, double-buffered
// cp.async. All fragment loads via ldmatrix.x4 (pitch 72 halves = 9x16B units ->
// conflict-free, 16B aligned).
// =============================================================================
#define HP 72                        // smem pitch (halves)
#define HBK 64                       // k per stage (halves)
#define GEMM_SMEM_H (2 * 128 * HP * 2 * 2)   // 73728 B

__global__ void __launch_bounds__(128) gemm_fp16(const __half* __restrict__ A,
                                                 const __half* __restrict__ Bm,
                                                 float* __restrict__ C,
                                                 int M, int N, int K)
{
    extern __shared__ __half shh[];
    __half* As = shh;                   // 2 x [128][HP]
    __half* Bs = shh + 2 * 128 * HP;    // 2 x [128][HP]

    const int tid  = threadIdx.x;
    const int lane = tid & 31, warp = tid >> 5;
    const int g  = lane >> 2, tg = lane & 3;
    const int wm = (warp >> 1) * 64, wn = (warp & 1) * 64;
    const int lr  = lane & 7;            // ldmatrix row within 8-group
    const int sel = lane >> 3;           // ldmatrix matrix selector 0..3

    const __half* Ag = A  + (size_t)blockIdx.y * 128 * K;
    const __half* Bg = Bm + (size_t)blockIdx.x * 128 * K;

    float c[4][8][4];
    #pragma unroll
    for (int i = 0; i < 4; i++)
        #pragma unroll
        for (int j = 0; j < 8; j++)
            #pragma unroll
            for (int t = 0; t < 4; t++) c[i][j][t] = 0.f;

    const int nkt = K / HBK;

#define HSTAGE(buf, kt) do {                                                 \
    __half* da = As + (buf) * 128 * HP;                                      \
    __half* db = Bs + (buf) * 128 * HP;                                      \
    const __half* sa = Ag + (size_t)(kt) * HBK;                              \
    const __half* sb = Bg + (size_t)(kt) * HBK;                              \
    _Pragma("unroll")                                                        \
    for (int i = 0; i < 8; i++){                                             \
        int idx = i * 128 + tid; int row = idx >> 3; int sg = (idx & 7) * 8; \
        cp16(da + row * HP + sg, sa + (size_t)row * K + sg);                 \
        cp16(db + row * HP + sg, sb + (size_t)row * K + sg);                 \
    }                                                                        \
} while (0)

    HSTAGE(0, 0); cp_commit();

    // ldmatrix lane offsets (constant across k-steps)
    const int a_roff = (sel & 1) * 8 + lr;     // row offset within 16-row tile
    const int a_coff = (sel >> 1) * 8;         // col offset (halves)
    const int b_toff = (sel >> 1);             // n-tile selector within pair
    const int b_coff = (sel & 1) * 8;          // col offset (halves)

    for (int kt = 0; kt < nkt; kt++) {
        if (kt + 1 < nkt) { HSTAGE((kt + 1) & 1, kt + 1); cp_commit(); cp_wait<1>(); }
        else              { cp_wait<0>(); }
        __syncthreads();

        const __half* Ab = As + (kt & 1) * 128 * HP;
        const __half* Bb = Bs + (kt & 1) * 128 * HP;

        #pragma unroll
        for (int ks = 0; ks < 4; ks++) {
            const int kch = ks * 16;               // halves
            unsigned a[4][4], bfr[8][2];
            #pragma unroll
            for (int f = 0; f < 4; f++)
                ldsm_x4(a[f][0], a[f][1], a[f][2], a[f][3],
                        Ab + (wm + f * 16 + a_roff) * HP + kch + a_coff);
            #pragma unroll
            for (int jj = 0; jj < 4; jj++)
                ldsm_x4(bfr[2*jj][0], bfr[2*jj][1], bfr[2*jj+1][0], bfr[2*jj+1][1],
                        Bb + (wn + (2*jj + b_toff) * 8 + lr) * HP + kch + b_coff);
            #pragma unroll
            for (int i = 0; i < 4; i++)
                #pragma unroll
                for (int j = 0; j < 8; j++)
                    mma_f16(c[i][j], a[i], bfr[j]);
        }
        __syncthreads();
    }
#undef HSTAGE

    #pragma unroll
    for (int i = 0; i < 4; i++) {
        int row0 = blockIdx.y * 128 + wm + i * 16 + g;
        #pragma unroll
        for (int j = 0; j < 8; j++) {
            int col = blockIdx.x * 128 + wn + j * 8 + 2 * tg;
            *(float2*)(C + (size_t)row0 * N + col)       = make_float2(c[i][j][0], c[i][j][1]);
            *(float2*)(C + (size_t)(row0 + 8) * N + col) = make_float2(c[i][j][2], c[i][j][3]);
        }
    }
}

// =============================================================================
// Per-head RMSNorm + RoPE core.  One warp per head; lane l owns dims
// {l, l+32, l+64, l+96}.
// =============================================================================
__device__ __forceinline__ void norm_rope_core(const float* __restrict__ inp,
                                               const float* __restrict__ w,
                                               const float* __restrict__ cosT,
                                               const float* __restrict__ sinT,
                                               int pos, int l,
                                               float& o0, float& o1, float& o2, float& o3)
{
    float v0 = inp[l], v1 = inp[l + 32], v2 = inp[l + 64], v3 = inp[l + 96];
    float ss = v0 * v0 + v1 * v1 + v2 * v2 + v3 * v3;
    #pragma unroll
    for (int off = 16; off; off >>= 1) ss += __shfl_xor_sync(0xffffffffu, ss, off);
    float rinv = rsqrtf(ss * (1.f / 128.f) + 1e-6f);
    v0 *= rinv * w[l];      v1 *= rinv * w[l + 32];
    v2 *= rinv * w[l + 64]; v3 *= rinv * w[l + 96];
    const float* c = cosT + (size_t)pos * 128;
    const float* s = sinT + (size_t)pos * 128;
    o0 = v0 * c[l]      - v2 * s[l];
    o1 = v1 * c[l + 32] - v3 * s[l + 32];
    o2 = v2 * c[l + 64] + v0 * s[l + 64];
    o3 = v3 * c[l + 96] + v1 * s[l + 96];
}

// Q: fp32 qkv (row stride NQKV) -> fp16 g_qh (row stride H*HD)
__global__ void q_norm_rope(const float* __restrict__ qkv, __half* __restrict__ qh,
                            const float* __restrict__ w,
                            const float* __restrict__ cosT, const float* __restrict__ sinT,
                            const int* __restrict__ pid)
{
    int bt = blockIdx.x;
    int h  = threadIdx.x >> 5;
    int l  = threadIdx.x & 31;
    const float* base = qkv + (size_t)bt * NQKV + h * HD_;
    float o0, o1, o2, o3;
    norm_rope_core(base, w, cosT, sinT, pid[bt], l, o0, o1, o2, o3);
    __half* ob = qh + (size_t)bt * (H_ * HD_) + h * HD_;
    ob[l]      = __float2half_rn(o0);
    ob[l + 32] = __float2half_rn(o1);
    ob[l + 64] = __float2half_rn(o2);
    ob[l + 96] = __float2half_rn(o3);
}

// K: qkv cols [4096,5120) -> exact fp32 kall (it is an output)
__global__ void k_norm_rope_scatter(const float* __restrict__ qkv,
                                    float* __restrict__ kall,
                                    const float* __restrict__ w,
                                    const float* __restrict__ cosT,
                                    const float* __restrict__ sinT,
                                    const int* __restrict__ pid)
{
    int bt = blockIdx.x;
    int b = bt >> 10, t = bt & 1023;
    int g = threadIdx.x >> 5;
    int l = threadIdx.x & 31;
    const float* src = qkv + (size_t)bt * NQKV + H_ * HD_ + g * HD_;
    float* dst = kall + (((size_t)(b * G_ + g) * SKV) + SPREV + t) * HD_;
    float o0, o1, o2, o3;
    norm_rope_core(src, w, cosT, sinT, pid[bt], l, o0, o1, o2, o3);
    dst[l] = o0; dst[l + 32] = o1; dst[l + 64] = o2; dst[l + 96] = o3;
}

// V in qkv cols [5120, 6144) -> v_all [b,g,SPREV+t,d]
__global__ void v_scatter(const float* __restrict__ qkv, float* __restrict__ vall)
{
    size_t i = (size_t)blockIdx.x * blockDim.x + threadIdx.x;  // 524288 float4s
    int d4 = i & 31;
    int g  = (i >> 5) & 7;
    int bt = (int)(i >> 8);
    int b = bt >> 10, t = bt & 1023;
    size_t src = (size_t)bt * (NQKV / 4) + (H_ * HD_ + G_ * HD_) / 4 + g * 32 + d4;
    size_t dst = (((size_t)(b * G_ + g) * SKV) + SPREV + t) * 32 + d4;
    ((float4*)vall)[dst] = ((const float4*)qkv)[src];
}

__global__ void prev_scatter(const float* __restrict__ pk, const float* __restrict__ pv,
                             float* __restrict__ kall, float* __restrict__ vall)
{
    size_t i = (size_t)blockIdx.x * blockDim.x + threadIdx.x;  // 524288 float4s
    int d4 = i & 31;
    int s  = (i >> 5) & 1023;
    int bg = (int)(i >> 15);
    size_t dst = ((size_t)bg * SKV + s) * 32 + d4;
    ((float4*)kall)[dst] = ((const float4*)pk)[i];
    ((float4*)vall)[dst] = ((const float4*)pv)[i];
}

// =============================================================================
// Full-fp16 tensor-core flash attention (m16n8k16, fp32 accum).
// Block 256 threads (8 warps) = (b, h, 128-query tile); KV tile = 64.
// All fragment loads via ldmatrix (Q/K/P non-trans, V trans).
// Smem (half): Qs 128x136, Ks 64x136, Vs 64x136, Ps 128x72. 88064 B -> 2 CTAs/SM.
// =============================================================================
#define ATTN_SMEM 88064

__global__ void __launch_bounds__(256, 2) attn_tc(const __half* __restrict__ qh,
                                                  const float* __restrict__ kall,
                                                  const float* __restrict__ vall,
                                                  __half* __restrict__ ctxh)
{
    extern __shared__ char smraw[];
    __half* Qs  = (__half*)smraw;                     // 128 x 136
    __half* Ks  = (__half*)(smraw + 34816);           // 64 x 136
    __half* Vs  = (__half*)(smraw + 52224);           // 64 x 136 (row-major [k][n])
    __half* PsH = (__half*)(smraw + 69632);           // 128 x 72

    const int t0 = blockIdx.x * 128;
    const int h  = blockIdx.y;
    const int b  = blockIdx.z;
    const int gk = h >> 2;             // kv group (H/G = 4)
    const int tid = threadIdx.x;
    const int lane = tid & 31, w = tid >> 5;
    const int g = lane >> 2, tg = lane & 3;
    const int lr  = lane & 7;
    const int sel = lane >> 3;

    // Q tile (fp16, rows stride H*HD)
    const __half* qbase = qh + (size_t)(b * TQ_ + t0) * (H_ * HD_) + h * HD_;
    #pragma unroll 4
    for (int i = tid; i < 128 * 16; i += 256) {
        int row = i >> 4, c8 = (i & 15) * 8;
        *(uint4*)(Qs + row * 136 + c8) =
            *(const uint4*)(qbase + (size_t)row * (H_ * HD_) + c8);
    }

    const int row0 = 16 * w + g;
    const int qp0 = SPREV + t0 + row0;
    const int qp1 = qp0 + 8;
    const int kv_lim = SPREV + t0 + 128;
    const float scale = 0.08838834764831845f;    // 1/sqrt(128)

    // ldmatrix lane offsets
    const int a_roff = (sel & 1) * 8 + lr;     // A-frag (Q, P): row offset
    const int a_coff = (sel >> 1) * 8;         //                col offset
    const int b_toff = (sel >> 1);             // B-frag (K): n-tile within pair
    const int b_coff = (sel & 1) * 8;          //             col offset
    const int vrow_l = lane & 15;              // V trans lane map
    const int vcol_l = (lane >> 4) << 3;

    const float* kb = kall + (size_t)(b * G_ + gk) * SKV * HD_;
    const float* vb = vall + (size_t)(b * G_ + gk) * SKV * HD_;

    float oacc[16][4];
    #pragma unroll
    for (int j = 0; j < 16; j++)
        #pragma unroll
        for (int t = 0; t < 4; t++) oacc[j][t] = 0.f;
    float m0 = -1e30f, m1 = -1e30f, l0 = 0.f, l1 = 0.f;

    __syncthreads();

    for (int j0 = 0; j0 < kv_lim; j0 += 64) {
        // K,V tiles: fp32 gmem -> fp16 smem (row-major both)
        #pragma unroll 4
        for (int i = tid; i < 64 * 32; i += 256) {
            int row = i >> 5, c4 = (i & 31) * 4;
            float4 k4 = *(const float4*)(kb + (size_t)(j0 + row) * HD_ + c4);
            __half2 h0 = __floats2half2_rn(k4.x, k4.y);
            __half2 h1 = __floats2half2_rn(k4.z, k4.w);
            uint2 u; u.x = *(unsigned*)&h0; u.y = *(unsigned*)&h1;
            *(uint2*)(Ks + row * 136 + c4) = u;
            float4 v4 = *(const float4*)(vb + (size_t)(j0 + row) * HD_ + c4);
            __half2 h2 = __floats2half2_rn(v4.x, v4.y);
            __half2 h3 = __floats2half2_rn(v4.z, v4.w);
            uint2 uv; uv.x = *(unsigned*)&h2; uv.y = *(unsigned*)&h3;
            *(uint2*)(Vs + row * 136 + c4) = uv;
        }
        __syncthreads();

        // ---- S = Q K^T  (fp16 m16n8k16, 8 k-steps, ldmatrix frags) ----
        float sacc[8][4];
        #pragma unroll
        for (int j = 0; j < 8; j++)
            #pragma unroll
            for (int t = 0; t < 4; t++) sacc[j][t] = 0.f;

        #pragma unroll
        for (int ks = 0; ks < 8; ks++) {
            const int kch = ks * 16;               // halves
            unsigned a[4];
            ldsm_x4(a[0], a[1], a[2], a[3],
                    Qs + (16 * w + a_roff) * 136 + kch + a_coff);
            unsigned bb[8][2];
            #pragma unroll
            for (int jj = 0; jj < 4; jj++)
                ldsm_x4(bb[2*jj][0], bb[2*jj][1], bb[2*jj+1][0], bb[2*jj+1][1],
                        Ks + ((2*jj + b_toff) * 8 + lr) * 136 + kch + b_coff);
            #pragma unroll
            for (int j = 0; j < 8; j++)
                mma_f16(sacc[j], a, bb[j]);
        }

        // ---- softmax on fragments ----
        const bool nm = (j0 + 63 > SPREV + t0);
        float ml0 = -1e30f, ml1 = -1e30f;
        #pragma unroll
        for (int j = 0; j < 8; j++) {
            if (nm) {
                int c0 = j0 + 8 * j + 2 * tg, c1 = c0 + 1;
                sacc[j][0] = (c0 <= qp0) ? sacc[j][0] * scale : -1e30f;
                sacc[j][1] = (c1 <= qp0) ? sacc[j][1] * scale : -1e30f;
                sacc[j][2] = (c0 <= qp1) ? sacc[j][2] * scale : -1e30f;
                sacc[j][3] = (c1 <= qp1) ? sacc[j][3] * scale : -1e30f;
            } else {
                sacc[j][0] *= scale; sacc[j][1] *= scale;
                sacc[j][2] *= scale; sacc[j][3] *= scale;
            }
            ml0 = fmaxf(ml0, fmaxf(sacc[j][0], sacc[j][1]));
            ml1 = fmaxf(ml1, fmaxf(sacc[j][2], sacc[j][3]));
        }
        ml0 = fmaxf(ml0, __shfl_xor_sync(0xffffffffu, ml0, 1));
        ml0 = fmaxf(ml0, __shfl_xor_sync(0xffffffffu, ml0, 2));
        ml1 = fmaxf(ml1, __shfl_xor_sync(0xffffffffu, ml1, 1));
        ml1 = fmaxf(ml1, __shfl_xor_sync(0xffffffffu, ml1, 2));
        float mn0 = fmaxf(m0, ml0), mn1 = fmaxf(m1, ml1);
        float al0 = __expf(m0 - mn0), al1 = __expf(m1 - mn1);

        float ls0 = 0.f, ls1 = 0.f;
        #pragma unroll
        for (int j = 0; j < 8; j++) {
            float p00 = __expf(sacc[j][0] - mn0);
            float p01 = __expf(sacc[j][1] - mn0);
            float p10 = __expf(sacc[j][2] - mn1);
            float p11 = __expf(sacc[j][3] - mn1);
            ls0 += p00 + p01; ls1 += p10 + p11;
            *(__half2*)(PsH + row0       * 72 + 8 * j + 2 * tg) = __floats2half2_rn(p00, p01);
            *(__half2*)(PsH + (row0 + 8) * 72 + 8 * j + 2 * tg) = __floats2half2_rn(p10, p11);
        }
        ls0 += __shfl_xor_sync(0xffffffffu, ls0, 1);
        ls0 += __shfl_xor_sync(0xffffffffu, ls0, 2);
        ls1 += __shfl_xor_sync(0xffffffffu, ls1, 1);
        ls1 += __shfl_xor_sync(0xffffffffu, ls1, 2);
        l0 = l0 * al0 + ls0;  m0 = mn0;
        l1 = l1 * al1 + ls1;  m1 = mn1;

        #pragma unroll
        for (int j = 0; j < 16; j++) {
            oacc[j][0] *= al0; oacc[j][1] *= al0;
            oacc[j][2] *= al1; oacc[j][3] *= al1;
        }
        __syncwarp();   // P rows of this warp: cross-lane STS->LDS visibility

        // ---- O += P V  (fp16; P a-frags via ldmatrix, V via ldmatrix.trans) ----
        #pragma unroll
        for (int ks = 0; ks < 4; ks++) {
            const int kch = ks * 16;
            unsigned a[4];
            ldsm_x4(a[0], a[1], a[2], a[3],
                    PsH + (16 * w + a_roff) * 72 + kch + a_coff);
            #pragma unroll
            for (int j2 = 0; j2 < 8; j2++) {
                unsigned r0, r1, r2, r3;
                const __half* vp = Vs + (ks * 16 + vrow_l) * 136 + j2 * 16 + vcol_l;
                ldsm_x4_trans(r0, r1, r2, r3, vp);
                unsigned b0[2] = { r0, r1 };
                unsigned b1[2] = { r2, r3 };
                mma_f16(oacc[2 * j2],     a, b0);
                mma_f16(oacc[2 * j2 + 1], a, b1);
            }
        }
        __syncthreads();
    }

    // epilogue: fp16 ctx (feeds fp16 out-projection A operand)
    float i0 = 1.f / l0, i1 = 1.f / l1;
    __half* c0p = ctxh + ((size_t)(b * TQ_ + t0 + row0)     * H_ + h) * HD_;
    __half* c1p = ctxh + ((size_t)(b * TQ_ + t0 + row0 + 8) * H_ + h) * HD_;
    #pragma unroll
    for (int j = 0; j < 16; j++) {
        int col = 8 * j + 2 * tg;
        *(__half2*)(c0p + col) = __floats2half2_rn(oacc[j][0] * i0, oacc[j][1] * i0);
        *(__half2*)(c1p + col) = __floats2half2_rn(oacc[j][2] * i1, oacc[j][3] * i1);
    }
}

// =============================================================================
// host launcher
// =============================================================================
template<typename T>
static T* sym_addr_t(const void* symbol)
{
    void* p = nullptr;
    cudaGetSymbolAddress(&p, symbol);
    return (T*)p;
}

extern "C" void kernel_launch(void* const* d_in, const int* in_sizes, int n_in,
                              void* d_out, int out_size)
{
    const float* x    = (const float*)d_in[0];
    const float* Wq   = (const float*)d_in[1];
    const float* Wk   = (const float*)d_in[2];
    const float* Wv   = (const float*)d_in[3];
    const float* Wo   = (const float*)d_in[4];
    const float* qw   = (const float*)d_in[5];
    const float* kw   = (const float*)d_in[6];
    const float* cosT = (const float*)d_in[7];
    const float* sinT = (const float*)d_in[8];
    const float* pk   = (const float*)d_in[9];
    const float* pv   = (const float*)d_in[10];
    const int*   pid  = (const int*)d_in[11];
    // d_in[12] = mask, computed analytically

    float* out  = (float*)d_out;                                    // B*T*DIN
    float* kall = out  + (size_t)B_ * TQ_ * DIN_;                   // B*G*SKV*HD
    float* vall = kall + (size_t)B_ * G_ * SKV * HD_;

    float*  qkv   = sym_addr_t<float>(g_qkv);
    __half* xh    = sym_addr_t<__half>(g_xh);
    __half* wqkvh = sym_addr_t<__half>(g_wqkvh);
    __half* woh   = sym_addr_t<__half>(g_woh);
    __half* qh    = sym_addr_t<__half>(g_qh);
    __half* ctxh  = sym_addr_t<__half>(g_ctxh);

    cudaFuncSetAttribute(gemm_fp16, cudaFuncAttributeMaxDynamicSharedMemorySize, GEMM_SMEM_H);
    cudaFuncSetAttribute(attn_tc,   cudaFuncAttributeMaxDynamicSharedMemorySize, ATTN_SMEM);

    // 1-5) fp32 -> fp16 convert pre-pass
    to_half<<< 8192, 256>>>((const float4*)x,  xh,                    2097152);
    to_half<<<16384, 256>>>((const float4*)Wq, wqkvh,                 4194304);
    to_half<<< 4096, 256>>>((const float4*)Wk, wqkvh + 16777216,      1048576);
    to_half<<< 4096, 256>>>((const float4*)Wv, wqkvh + 20971520,      1048576);
    to_half<<<16384, 256>>>((const float4*)Wo, woh,                   4194304);

    // 6) fused QKV projection: [2048 x 6144] = xh @ [Wq;Wk;Wv]^T  (fp32 out)
    gemm_fp16<<<dim3(NQKV / 128, BT_ / 128), 128, GEMM_SMEM_H>>>(xh, wqkvh, qkv, BT_, NQKV, DIN_);

    // 7) prev kv cache copy
    prev_scatter<<<2048, 256>>>(pk, pv, kall, vall);

    // 8-10) norm + rope + kv assembly
    q_norm_rope<<<BT_, H_ * 32>>>(qkv, qh, qw, cosT, sinT, pid);
    k_norm_rope_scatter<<<BT_, G_ * 32>>>(qkv, kall, kw, cosT, sinT, pid);
    v_scatter<<<2048, 256>>>(qkv, vall);

    // 11) attention (full fp16, ldmatrix everywhere)
    attn_tc<<<dim3(TQ_ / 128, H_, B_), 256, ATTN_SMEM>>>(qh, kall, vall, ctxh);

    // 12) output projection
    gemm_fp16<<<dim3(DIN_ / 128, BT_ / 128), 128, GEMM_SMEM_H>>>(ctxh, woh, out, BT_, DIN_, DIN_);

    (void)in_sizes; (void)n_in; (void)out_size;
}

// round 14
// speedup vs baseline: 22.5296x; 1.0498x over previous
#include <cuda_runtime.h>
#include <cuda_bf16.h>
#include <cuda_fp16.h>
#include <cstdint>

// Problem constants
#define B_    2
#define TQ_   1024
#define DIN_  4096
#define H_    32
#define G_    8
#define HD_   128
#define SPREV 1024
#define SKV   2048          // SPREV + TQ
#define BT_   (B_*TQ_)      // 2048
#define NQKV  6144          // H*HD + 2*G*HD

// ---------------- scratch (no allocation allowed -> __device__ globals) ---------
__device__ float  g_qkv [(size_t)BT_ * NQKV];        // fused q|k|v projections (fp32)
__device__ __half g_xh  [(size_t)BT_ * DIN_];        // fp16 x
__device__ __half g_wqkvh[(size_t)NQKV * DIN_];      // fp16 [Wq;Wk;Wv]
__device__ __half g_woh [(size_t)DIN_ * H_ * HD_];   // fp16 Wo
__device__ __half g_qh  [(size_t)BT_ * H_ * HD_];    // fp16 Q (post norm+rope)
__device__ __half g_ctxh[(size_t)BT_ * H_ * HD_];    // fp16 attention output
__device__ __half g_kh  [(size_t)B_ * G_ * SKV * HD_]; // fp16 mirror of k_all
__device__ __half g_vh  [(size_t)B_ * G_ * SKV * HD_]; // fp16 mirror of v_all

// =============================================================================
// helpers
// =============================================================================
__device__ __forceinline__ void cp16(void* s, const void* g){
    unsigned sa = (unsigned)__cvta_generic_to_shared(s);
    asm volatile("cp.async.cg.shared.global [%0], [%1], 16;\n" :: "r"(sa), "l"(g));
}
__device__ __forceinline__ void cp_commit(){ asm volatile("cp.async.commit_group;\n" ::); }
template<int NN> __device__ __forceinline__ void cp_wait(){
    asm volatile("cp.async.wait_group %0;\n" :: "n"(NN));
}
__device__ __forceinline__ void mma_f16(float* c, const unsigned* a, const unsigned* b){
    asm volatile(
      "mma.sync.aligned.m16n8k16.row.col.f32.f16.f16.f32 "
      "{%0,%1,%2,%3}, {%4,%5,%6,%7}, {%8,%9}, {%0,%1,%2,%3};"
      : "+f"(c[0]), "+f"(c[1]), "+f"(c[2]), "+f"(c[3])
      : "r"(a[0]), "r"(a[1]), "r"(a[2]), "r"(a[3]), "r"(b[0]), "r"(b[1]));
}
__device__ __forceinline__ void ldsm_x4(unsigned& r0, unsigned& r1,
                                        unsigned& r2, unsigned& r3,
                                        const void* p){
    unsigned sa = (unsigned)__cvta_generic_to_shared(p);
    asm volatile("ldmatrix.sync.aligned.m8n8.x4.shared.b16 {%0,%1,%2,%3}, [%4];"
                 : "=r"(r0), "=r"(r1), "=r"(r2), "=r"(r3) : "r"(sa));
}
__device__ __forceinline__ void ldsm_x4_trans(unsigned& r0, unsigned& r1,
                                              unsigned& r2, unsigned& r3,
                                              const void* p){
    unsigned sa = (unsigned)__cvta_generic_to_shared(p);
    asm volatile("ldmatrix.sync.aligned.m8n8.x4.trans.shared.b16 {%0,%1,%2,%3}, [%4];"
                 : "=r"(r0), "=r"(r1), "=r"(r2), "=r"(r3) : "r"(sa));
}

// =============================================================================
// fused fp32 -> fp16 convert pre-pass (x, Wq, Wk, Wv, Wo in one launch)
// =============================================================================
__global__ void to_half_all(const float4* __restrict__ x,  const float4* __restrict__ wq,
                            const float4* __restrict__ wk, const float4* __restrict__ wv,
                            const float4* __restrict__ wo)
{
    size_t i = (size_t)blockIdx.x * 256 + threadIdx.x;      // 12,582,912 float4s
    const float4* s; __half* d; size_t off;
    if      (i <  2097152u) { s = x;  d = g_xh;              off = i; }
    else if (i <  6291456u) { s = wq; d = g_wqkvh;           off = i - 2097152u; }
    else if (i <  7340032u) { s = wk; d = g_wqkvh + 16777216; off = i - 6291456u; }
    else if (i <  8388608u) { s = wv; d = g_wqkvh + 20971520; off = i - 7340032u; }
    else                    { s = wo; d = g_woh;             off = i - 8388608u; }
    float4 v = s[off];
    __half2 h0 = __floats2half2_rn(v.x, v.y);
    __half2 h1 = __floats2half2_rn(v.z, v.w);
    uint2 u; u.x = *(unsigned*)&h0; u.y = *(unsigned*)&h1;
    ((uint2*)d)[off] = u;
}

// =============================================================================
// fp16 tensor-core NT GEMM: C[m,n] = sum_k A[m,k]*B[n,k], fp32 accumulate.
// Tile 128x128x64, 128 threads (4 warps, each 64x64), m16n8k16, double-buffered
// cp.async, ldmatrix fragment loads (pitch 72 halves -> conflict-free).
// =============================================================================
#define HP 72                        // smem pitch (halves)
#define HBK 64                       // k per stage (halves)
#define GEMM_SMEM_H (2 * 128 * HP * 2 * 2)   // 73728 B

__global__ void __launch_bounds__(128) gemm_fp16(const __half* __restrict__ A,
                                                 const __half* __restrict__ Bm,
                                                 float* __restrict__ C,
                                                 int M, int N, int K)
{
    extern __shared__ __half shh[];
    __half* As = shh;                   // 2 x [128][HP]
    __half* Bs = shh + 2 * 128 * HP;    // 2 x [128][HP]

    const int tid  = threadIdx.x;
    const int lane = tid & 31, warp = tid >> 5;
    const int g  = lane >> 2, tg = lane & 3;
    const int wm = (warp >> 1) * 64, wn = (warp & 1) * 64;
    const int lr  = lane & 7;
    const int sel = lane >> 3;

    const __half* Ag = A  + (size_t)blockIdx.y * 128 * K;
    const __half* Bg = Bm + (size_t)blockIdx.x * 128 * K;

    float c[4][8][4];
    #pragma unroll
    for (int i = 0; i < 4; i++)
        #pragma unroll
        for (int j = 0; j < 8; j++)
            #pragma unroll
            for (int t = 0; t < 4; t++) c[i][j][t] = 0.f;

    const int nkt = K / HBK;

#define HSTAGE(buf, kt) do {                                                 \
    __half* da = As + (buf) * 128 * HP;                                      \
    __half* db = Bs + (buf) * 128 * HP;                                      \
    const __half* sa = Ag + (size_t)(kt) * HBK;                              \
    const __half* sb = Bg + (size_t)(kt) * HBK;                              \
    _Pragma("unroll")                                                        \
    for (int i = 0; i < 8; i++){                                             \
        int idx = i * 128 + tid; int row = idx >> 3; int sg = (idx & 7) * 8; \
        cp16(da + row * HP + sg, sa + (size_t)row * K + sg);                 \
        cp16(db + row * HP + sg, sb + (size_t)row * K + sg);                 \
    }                                                                        \
} while (0)

    HSTAGE(0, 0); cp_commit();

    const int a_roff = (sel & 1) * 8 + lr;
    const int a_coff = (sel >> 1) * 8;
    const int b_toff = (sel >> 1);
    const int b_coff = (sel & 1) * 8;

    for (int kt = 0; kt < nkt; kt++) {
        if (kt + 1 < nkt) { HSTAGE((kt + 1) & 1, kt + 1); cp_commit(); cp_wait<1>(); }
        else              { cp_wait<0>(); }
        __syncthreads();

        const __half* Ab = As + (kt & 1) * 128 * HP;
        const __half* Bb = Bs + (kt & 1) * 128 * HP;

        #pragma unroll
        for (int ks = 0; ks < 4; ks++) {
            const int kch = ks * 16;
            unsigned a[4][4], bfr[8][2];
            #pragma unroll
            for (int f = 0; f < 4; f++)
                ldsm_x4(a[f][0], a[f][1], a[f][2], a[f][3],
                        Ab + (wm + f * 16 + a_roff) * HP + kch + a_coff);
            #pragma unroll
            for (int jj = 0; jj < 4; jj++)
                ldsm_x4(bfr[2*jj][0], bfr[2*jj][1], bfr[2*jj+1][0], bfr[2*jj+1][1],
                        Bb + (wn + (2*jj + b_toff) * 8 + lr) * HP + kch + b_coff);
            #pragma unroll
            for (int i = 0; i < 4; i++)
                #pragma unroll
                for (int j = 0; j < 8; j++)
                    mma_f16(c[i][j], a[i], bfr[j]);
        }
        __syncthreads();
    }
#undef HSTAGE

    #pragma unroll
    for (int i = 0; i < 4; i++) {
        int row0 = blockIdx.y * 128 + wm + i * 16 + g;
        #pragma unroll
        for (int j = 0; j < 8; j++) {
            int col = blockIdx.x * 128 + wn + j * 8 + 2 * tg;
            *(float2*)(C + (size_t)row0 * N + col)       = make_float2(c[i][j][0], c[i][j][1]);
            *(float2*)(C + (size_t)(row0 + 8) * N + col) = make_float2(c[i][j][2], c[i][j][3]);
        }
    }
}

// =============================================================================
// Per-head RMSNorm + RoPE core.  One warp per head; lane l owns dims
// {l, l+32, l+64, l+96}.
// =============================================================================
__device__ __forceinline__ void norm_rope_core(const float* __restrict__ inp,
                                               const float* __restrict__ w,
                                               const float* __restrict__ cosT,
                                               const float* __restrict__ sinT,
                                               int pos, int l,
                                               float& o0, float& o1, float& o2, float& o3)
{
    float v0 = inp[l], v1 = inp[l + 32], v2 = inp[l + 64], v3 = inp[l + 96];
    float ss = v0 * v0 + v1 * v1 + v2 * v2 + v3 * v3;
    #pragma unroll
    for (int off = 16; off; off >>= 1) ss += __shfl_xor_sync(0xffffffffu, ss, off);
    float rinv = rsqrtf(ss * (1.f / 128.f) + 1e-6f);
    v0 *= rinv * w[l];      v1 *= rinv * w[l + 32];
    v2 *= rinv * w[l + 64]; v3 *= rinv * w[l + 96];
    const float* c = cosT + (size_t)pos * 128;
    const float* s = sinT + (size_t)pos * 128;
    o0 = v0 * c[l]      - v2 * s[l];
    o1 = v1 * c[l + 32] - v3 * s[l + 32];
    o2 = v2 * c[l + 64] + v0 * s[l + 64];
    o3 = v3 * c[l + 96] + v1 * s[l + 96];
}

// Q: fp32 qkv (row stride NQKV) -> fp16 g_qh
__global__ void q_norm_rope(const float* __restrict__ qkv, __half* __restrict__ qh,
                            const float* __restrict__ w,
                            const float* __restrict__ cosT, const float* __restrict__ sinT,
                            const int* __restrict__ pid)
{
    int bt = blockIdx.x;
    int h  = threadIdx.x >> 5;
    int l  = threadIdx.x & 31;
    const float* base = qkv + (size_t)bt * NQKV + h * HD_;
    float o0, o1, o2, o3;
    norm_rope_core(base, w, cosT, sinT, pid[bt], l, o0, o1, o2, o3);
    __half* ob = qh + (size_t)bt * (H_ * HD_) + h * HD_;
    ob[l]      = __float2half_rn(o0);
    ob[l + 32] = __float2half_rn(o1);
    ob[l + 64] = __float2half_rn(o2);
    ob[l + 96] = __float2half_rn(o3);
}

// K: qkv cols [4096,5120) -> exact fp32 kall (output) + fp16 mirror
__global__ void k_norm_rope_scatter(const float* __restrict__ qkv,
                                    float* __restrict__ kall,
                                    __half* __restrict__ kh,
                                    const float* __restrict__ w,
                                    const float* __restrict__ cosT,
                                    const float* __restrict__ sinT,
                                    const int* __restrict__ pid)
{
    int bt = blockIdx.x;
    int b = bt >> 10, t = bt & 1023;
    int g = threadIdx.x >> 5;
    int l = threadIdx.x & 31;
    const float* src = qkv + (size_t)bt * NQKV + H_ * HD_ + g * HD_;
    size_t ro = (((size_t)(b * G_ + g) * SKV) + SPREV + t) * HD_;
    float o0, o1, o2, o3;
    norm_rope_core(src, w, cosT, sinT, pid[bt], l, o0, o1, o2, o3);
    float* dst = kall + ro;
    dst[l] = o0; dst[l + 32] = o1; dst[l + 64] = o2; dst[l + 96] = o3;
    __half* dh = kh + ro;
    dh[l]      = __float2half_rn(o0);
    dh[l + 32] = __float2half_rn(o1);
    dh[l + 64] = __float2half_rn(o2);
    dh[l + 96] = __float2half_rn(o3);
}

// V in qkv cols [5120, 6144) -> fp32 v_all + fp16 mirror
__global__ void v_scatter(const float* __restrict__ qkv, float* __restrict__ vall,
                          __half* __restrict__ vh)
{
    size_t i = (size_t)blockIdx.x * blockDim.x + threadIdx.x;  // 524288 float4s
    int d4 = i & 31;
    int g  = (i >> 5) & 7;
    int bt = (int)(i >> 8);
    int b = bt >> 10, t = bt & 1023;
    size_t src = (size_t)bt * (NQKV / 4) + (H_ * HD_ + G_ * HD_) / 4 + g * 32 + d4;
    size_t dst = (((size_t)(b * G_ + g) * SKV) + SPREV + t) * 32 + d4;
    float4 v = ((const float4*)qkv)[src];
    ((float4*)vall)[dst] = v;
    __half2 h0 = __floats2half2_rn(v.x, v.y);
    __half2 h1 = __floats2half2_rn(v.z, v.w);
    uint2 u; u.x = *(unsigned*)&h0; u.y = *(unsigned*)&h1;
    ((uint2*)vh)[dst] = u;
}

// prev_k/prev_v -> fp32 caches + fp16 mirrors
__global__ void prev_scatter(const float* __restrict__ pk, const float* __restrict__ pv,
                             float* __restrict__ kall, float* __restrict__ vall,
                             __half* __restrict__ kh, __half* __restrict__ vh)
{
    size_t i = (size_t)blockIdx.x * blockDim.x + threadIdx.x;  // 524288 float4s
    int d4 = i & 31;
    int s  = (i >> 5) & 1023;
    int bg = (int)(i >> 15);
    size_t dst = ((size_t)bg * SKV + s) * 32 + d4;
    float4 k = ((const float4*)pk)[i];
    float4 v = ((const float4*)pv)[i];
    ((float4*)kall)[dst] = k;
    ((float4*)vall)[dst] = v;
    __half2 a0 = __floats2half2_rn(k.x, k.y), a1 = __floats2half2_rn(k.z, k.w);
    __half2 b0 = __floats2half2_rn(v.x, v.y), b1 = __floats2half2_rn(v.z, v.w);
    uint2 uk; uk.x = *(unsigned*)&a0; uk.y = *(unsigned*)&a1;
    uint2 uv; uv.x = *(unsigned*)&b0; uv.y = *(unsigned*)&b1;
    ((uint2*)kh)[dst] = uk;
    ((uint2*)vh)[dst] = uv;
}

// =============================================================================
// Full-fp16 tensor-core flash attention (m16n8k16, fp32 accum).
// Block 256 threads (8 warps) = (b, h, 128-query tile); KV tile = 64.
// K/V read from fp16 mirrors via cp.async; ldmatrix everywhere.
// Smem (half): Qs 128x136, Ks 64x136, Vs 64x136, Ps 128x72. 88064 B -> 2 CTAs/SM.
// =============================================================================
#define ATTN_SMEM 88064

__global__ void __launch_bounds__(256, 2) attn_tc(const __half* __restrict__ qh,
                                                  const __half* __restrict__ kh,
                                                  const __half* __restrict__ vh,
                                                  __half* __restrict__ ctxh)
{
    extern __shared__ char smraw[];
    __half* Qs  = (__half*)smraw;                     // 128 x 136
    __half* Ks  = (__half*)(smraw + 34816);           // 64 x 136
    __half* Vs  = (__half*)(smraw + 52224);           // 64 x 136 (row-major [k][n])
    __half* PsH = (__half*)(smraw + 69632);           // 128 x 72

    const int t0 = blockIdx.x * 128;
    const int h  = blockIdx.y;
    const int b  = blockIdx.z;
    const int gk = h >> 2;             // kv group (H/G = 4)
    const int tid = threadIdx.x;
    const int lane = tid & 31, w = tid >> 5;
    const int g = lane >> 2, tg = lane & 3;
    const int lr  = lane & 7;
    const int sel = lane >> 3;

    // Q tile (fp16, rows stride H*HD)
    const __half* qbase = qh + (size_t)(b * TQ_ + t0) * (H_ * HD_) + h * HD_;
    #pragma unroll 4
    for (int i = tid; i < 128 * 16; i += 256) {
        int row = i >> 4, c8 = (i & 15) * 8;
        *(uint4*)(Qs + row * 136 + c8) =
            *(const uint4*)(qbase + (size_t)row * (H_ * HD_) + c8);
    }

    const int row0 = 16 * w + g;
    const int qp0 = SPREV + t0 + row0;
    const int qp1 = qp0 + 8;
    const int kv_lim = SPREV + t0 + 128;
    const float scale = 0.08838834764831845f;    // 1/sqrt(128)

    const int a_roff = (sel & 1) * 8 + lr;
    const int a_coff = (sel >> 1) * 8;
    const int b_toff = (sel >> 1);
    const int b_coff = (sel & 1) * 8;
    const int vrow_l = lane & 15;
    const int vcol_l = (lane >> 4) << 3;

    const __half* kb = kh + (size_t)(b * G_ + gk) * SKV * HD_;
    const __half* vb = vh + (size_t)(b * G_ + gk) * SKV * HD_;

    float oacc[16][4];
    #pragma unroll
    for (int j = 0; j < 16; j++)
        #pragma unroll
        for (int t = 0; t < 4; t++) oacc[j][t] = 0.f;
    float m0 = -1e30f, m1 = -1e30f, l0 = 0.f, l1 = 0.f;

    __syncthreads();

    for (int j0 = 0; j0 < kv_lim; j0 += 64) {
        // K,V tiles via cp.async (fp16 source, straight copy)
        #pragma unroll
        for (int i = tid; i < 64 * 16; i += 256) {
            int row = i >> 4, sg = (i & 15) * 8;
            cp16(Ks + row * 136 + sg, kb + (size_t)(j0 + row) * HD_ + sg);
            cp16(Vs + row * 136 + sg, vb + (size_t)(j0 + row) * HD_ + sg);
        }
        cp_commit();
        cp_wait<0>();
        __syncthreads();

        // ---- S = Q K^T  (fp16 m16n8k16, 8 k-steps, ldmatrix frags) ----
        float sacc[8][4];
        #pragma unroll
        for (int j = 0; j < 8; j++)
            #pragma unroll
            for (int t = 0; t < 4; t++) sacc[j][t] = 0.f;

        #pragma unroll
        for (int ks = 0; ks < 8; ks++) {
            const int kch = ks * 16;
            unsigned a[4];
            ldsm_x4(a[0], a[1], a[2], a[3],
                    Qs + (16 * w + a_roff) * 136 + kch + a_coff);
            unsigned bb[8][2];
            #pragma unroll
            for (int jj = 0; jj < 4; jj++)
                ldsm_x4(bb[2*jj][0], bb[2*jj][1], bb[2*jj+1][0], bb[2*jj+1][1],
                        Ks + ((2*jj + b_toff) * 8 + lr) * 136 + kch + b_coff);
            #pragma unroll
            for (int j = 0; j < 8; j++)
                mma_f16(sacc[j], a, bb[j]);
        }

        // ---- softmax on fragments ----
        const bool nm = (j0 + 63 > SPREV + t0);
        float ml0 = -1e30f, ml1 = -1e30f;
        #pragma unroll
        for (int j = 0; j < 8; j++) {
            if (nm) {
                int c0 = j0 + 8 * j + 2 * tg, c1 = c0 + 1;
                sacc[j][0] = (c0 <= qp0) ? sacc[j][0] * scale : -1e30f;
                sacc[j][1] = (c1 <= qp0) ? sacc[j][1] * scale : -1e30f;
                sacc[j][2] = (c0 <= qp1) ? sacc[j][2] * scale : -1e30f;
                sacc[j][3] = (c1 <= qp1) ? sacc[j][3] * scale : -1e30f;
            } else {
                sacc[j][0] *= scale; sacc[j][1] *= scale;
                sacc[j][2] *= scale; sacc[j][3] *= scale;
            }
            ml0 = fmaxf(ml0, fmaxf(sacc[j][0], sacc[j][1]));
            ml1 = fmaxf(ml1, fmaxf(sacc[j][2], sacc[j][3]));
        }
        ml0 = fmaxf(ml0, __shfl_xor_sync(0xffffffffu, ml0, 1));
        ml0 = fmaxf(ml0, __shfl_xor_sync(0xffffffffu, ml0, 2));
        ml1 = fmaxf(ml1, __shfl_xor_sync(0xffffffffu, ml1, 1));
        ml1 = fmaxf(ml1, __shfl_xor_sync(0xffffffffu, ml1, 2));
        float mn0 = fmaxf(m0, ml0), mn1 = fmaxf(m1, ml1);
        float al0 = __expf(m0 - mn0), al1 = __expf(m1 - mn1);

        float ls0 = 0.f, ls1 = 0.f;
        #pragma unroll
        for (int j = 0; j < 8; j++) {
            float p00 = __expf(sacc[j][0] - mn0);
            float p01 = __expf(sacc[j][1] - mn0);
            float p10 = __expf(sacc[j][2] - mn1);
            float p11 = __expf(sacc[j][3] - mn1);
            ls0 += p00 + p01; ls1 += p10 + p11;
            *(__half2*)(PsH + row0       * 72 + 8 * j + 2 * tg) = __floats2half2_rn(p00, p01);
            *(__half2*)(PsH + (row0 + 8) * 72 + 8 * j + 2 * tg) = __floats2half2_rn(p10, p11);
        }
        ls0 += __shfl_xor_sync(0xffffffffu, ls0, 1);
        ls0 += __shfl_xor_sync(0xffffffffu, ls0, 2);
        ls1 += __shfl_xor_sync(0xffffffffu, ls1, 1);
        ls1 += __shfl_xor_sync(0xffffffffu, ls1, 2);
        l0 = l0 * al0 + ls0;  m0 = mn0;
        l1 = l1 * al1 + ls1;  m1 = mn1;

        #pragma unroll
        for (int j = 0; j < 16; j++) {
            oacc[j][0] *= al0; oacc[j][1] *= al0;
            oacc[j][2] *= al1; oacc[j][3] *= al1;
        }
        __syncwarp();   // P rows of this warp: cross-lane STS->LDS visibility

        // ---- O += P V  (fp16; P via ldmatrix, V via ldmatrix.trans) ----
        #pragma unroll
        for (int ks = 0; ks < 4; ks++) {
            const int kch = ks * 16;
            unsigned a[4];
            ldsm_x4(a[0], a[1], a[2], a[3],
                    PsH + (16 * w + a_roff) * 72 + kch + a_coff);
            #pragma unroll
            for (int j2 = 0; j2 < 8; j2++) {
                unsigned r0, r1, r2, r3;
                const __half* vp = Vs + (ks * 16 + vrow_l) * 136 + j2 * 16 + vcol_l;
                ldsm_x4_trans(r0, r1, r2, r3, vp);
                unsigned b0[2] = { r0, r1 };
                unsigned b1[2] = { r2, r3 };
                mma_f16(oacc[2 * j2],     a, b0);
                mma_f16(oacc[2 * j2 + 1], a, b1);
            }
        }
        __syncthreads();
    }

    // epilogue: fp16 ctx (feeds fp16 out-projection A operand)
    float i0 = 1.f / l0, i1 = 1.f / l1;
    __half* c0p = ctxh + ((size_t)(b * TQ_ + t0 + row0)     * H_ + h) * HD_;
    __half* c1p = ctxh + ((size_t)(b * TQ_ + t0 + row0 + 8) * H_ + h) * HD_;
    #pragma unroll
    for (int j = 0; j < 16; j++) {
        int col = 8 * j + 2 * tg;
        *(__half2*)(c0p + col) = __floats2half2_rn(oacc[j][0] * i0, oacc[j][1] * i0);
        *(__half2*)(c1p + col) = __floats2half2_rn(oacc[j][2] * i1, oacc[j][3] * i1);
    }
}

// =============================================================================
// host launcher
// =============================================================================
template<typename T>
static T* sym_addr_t(const void* symbol)
{
    void* p = nullptr;
    cudaGetSymbolAddress(&p, symbol);
    return (T*)p;
}

extern "C" void kernel_launch(void* const* d_in, const int* in_sizes, int n_in,
                              void* d_out, int out_size)
{
    const float* x    = (const float*)d_in[0];
    const float* Wq   = (const float*)d_in[1];
    const float* Wk   = (const float*)d_in[2];
    const float* Wv   = (const float*)d_in[3];
    const float* Wo   = (const float*)d_in[4];
    const float* qw   = (const float*)d_in[5];
    const float* kw   = (const float*)d_in[6];
    const float* cosT = (const float*)d_in[7];
    const float* sinT = (const float*)d_in[8];
    const float* pk   = (const float*)d_in[9];
    const float* pv   = (const float*)d_in[10];
    const int*   pid  = (const int*)d_in[11];
    // d_in[12] = mask, computed analytically

    float* out  = (float*)d_out;                                    // B*T*DIN
    float* kall = out  + (size_t)B_ * TQ_ * DIN_;                   // B*G*SKV*HD
    float* vall = kall + (size_t)B_ * G_ * SKV * HD_;

    float*  qkv   = sym_addr_t<float>(g_qkv);
    __half* wqkvh = sym_addr_t<__half>(g_wqkvh);
    __half* xh    = sym_addr_t<__half>(g_xh);
    __half* woh   = sym_addr_t<__half>(g_woh);
    __half* qh    = sym_addr_t<__half>(g_qh);
    __half* ctxh  = sym_addr_t<__half>(g_ctxh);
    __half* kh    = sym_addr_t<__half>(g_kh);
    __half* vh    = sym_addr_t<__half>(g_vh);

    cudaFuncSetAttribute(gemm_fp16, cudaFuncAttributeMaxDynamicSharedMemorySize, GEMM_SMEM_H);
    cudaFuncSetAttribute(attn_tc,   cudaFuncAttributeMaxDynamicSharedMemorySize, ATTN_SMEM);

    // 1) fused fp32 -> fp16 convert pre-pass (x + all weights, one launch)
    to_half_all<<<49152, 256>>>((const float4*)x,  (const float4*)Wq,
                                (const float4*)Wk, (const float4*)Wv,
                                (const float4*)Wo);

    // 2) fused QKV projection: [2048 x 6144] = xh @ [Wq;Wk;Wv]^T  (fp32 out)
    gemm_fp16<<<dim3(NQKV / 128, BT_ / 128), 128, GEMM_SMEM_H>>>(xh, wqkvh, qkv, BT_, NQKV, DIN_);

    // 3) prev kv cache copy (fp32 outputs + fp16 mirrors)
    prev_scatter<<<2048, 256>>>(pk, pv, kall, vall, kh, vh);

    // 4-6) norm + rope + kv assembly (dual-precision writes)
    q_norm_rope<<<BT_, H_ * 32>>>(qkv, qh, qw, cosT, sinT, pid);
    k_norm_rope_scatter<<<BT_, G_ * 32>>>(qkv, kall, kh, kw, cosT, sinT, pid);
    v_scatter<<<2048, 256>>>(qkv, vall, vh);

    // 7) attention (full fp16, cp.async KV tiles)
    attn_tc<<<dim3(TQ_ / 128, H_, B_), 256, ATTN_SMEM>>>(qh, kh, vh, ctxh);

    // 8) output projection
    gemm_fp16<<<dim3(DIN_ / 128, BT_ / 128), 128, GEMM_SMEM_H>>>(ctxh, woh, out, BT_, DIN_, DIN_);

    (void)in_sizes; (void)n_in; (void)out_size;
}